// round 12
// baseline (speedup 1.0000x reference)
#include <cuda_runtime.h>
#include <math.h>

#define NB   4
#define NTOK 65536
#define CD   256
#define LD   64
#define SD   64
#define TT   64
#define BPB  74
#define NTILE 1024
#define PH 260
#define PL 68

__device__ float g_w[(size_t)NB * NTOK * SD];   // softmax weights (tf32, row-major)
__device__ float g_M[NB * SD * LD];             // accumulated w^T @ shared
__device__ float g_wsum[NB * SD];
__device__ float g_WshP[4 * 4096];              // tf32+perm Wsh (4 k-chunks)
__device__ float g_WasnP[2 * 4096];             // tf32+perm Wasn (2 k-chunks)
__device__ float g_WinP[8 * 4096];              // tf32+perm Win (kt*2+h)
__device__ float g_WoutP[4 * 4096];             // tf32+perm Wout (cc)
__device__ float g_stP[NB * 4 * 4096];          // tf32+perm st (b, cc)

__device__ __forceinline__ float geluf(float x) {
    return 0.5f * x * (1.0f + erff(x * 0.70710678118654752f));
}
__device__ __forceinline__ float sigm(float x) { return 1.0f / (1.0f + __expf(-x)); }

__device__ __forceinline__ float totf(float x) {
    unsigned r;
    asm("cvt.rna.tf32.f32 %0, %1;" : "=r"(r) : "f"(x));
    return __uint_as_float(r);
}

// fragment-order index for a 64x64 B chunk: element B[k][c]
__device__ __forceinline__ int pidx(int k, int c) {
    return ((k >> 3) * 4 + (k & 3)) * 128 + c * 2 + ((k >> 2) & 1);
}

__device__ __forceinline__ void mma8(float (&d)[4], const unsigned (&a)[4], const unsigned (&b)[2]) {
    asm volatile("mma.sync.aligned.m16n8k8.row.col.f32.tf32.tf32.f32 "
                 "{%0,%1,%2,%3}, {%4,%5,%6,%7}, {%8,%9}, {%0,%1,%2,%3};"
                 : "+f"(d[0]), "+f"(d[1]), "+f"(d[2]), "+f"(d[3])
                 : "r"(a[0]), "r"(a[1]), "r"(a[2]), "r"(a[3]), "r"(b[0]), "r"(b[1]));
}

// warp mma: acc(16x32) += A(64 rows x 64 k, smem, pitch lda) @ B(64x64 perm chunk in GMEM).
// warp tile rows wr*16.., cols wc*32 + t*8. B fragments = coalesced LDG.64.
__device__ __forceinline__ void mma_gB(const float* __restrict__ sA, int lda,
                                       const float* __restrict__ gB,
                                       int wr, int wc, int g, int q, float (&acc)[4][4])
{
#pragma unroll
    for (int k8 = 0; k8 < 8; k8++) {
        const float* Ab = sA + (wr * 16 + g) * lda + k8 * 8 + q;
        unsigned a[4] = { __float_as_uint(Ab[0]), __float_as_uint(Ab[8 * lda]),
                          __float_as_uint(Ab[4]), __float_as_uint(Ab[8 * lda + 4]) };
        const float2* Bb = reinterpret_cast<const float2*>(gB + (k8 * 4 + q) * 128 + (wc * 32 + g) * 2);
#pragma unroll
        for (int t = 0; t < 4; t++) {
            float2 bp = Bb[t * 8];
            unsigned b[2] = { __float_as_uint(bp.x), __float_as_uint(bp.y) };
            mma8(acc[t], a, b);
        }
    }
}

// ---------- scalar micro-kernels (k2 + k1's GEMM4') ----------
__device__ __forceinline__ void mm64(const float* __restrict__ A, int ald,
                                     const float* __restrict__ B, int bld,
                                     int tr, int tc, float (&acc)[4][4])
{
#pragma unroll 8
    for (int kk = 0; kk < 64; kk++) {
        float4 b4 = *reinterpret_cast<const float4*>(B + kk * bld + tc * 4);
        float a[4] = { A[tr * ald + kk], A[(tr + 16) * ald + kk],
                       A[(tr + 32) * ald + kk], A[(tr + 48) * ald + kk] };
        float bb[4] = { b4.x, b4.y, b4.z, b4.w };
#pragma unroll
        for (int i = 0; i < 4; i++)
#pragma unroll
            for (int j = 0; j < 4; j++) acc[i][j] = fmaf(a[i], bb[j], acc[i][j]);
    }
}

__device__ __forceinline__ void mmT64(const float* __restrict__ A, int ald,
                                      const float* __restrict__ B, int bld,
                                      int tr, int tc, float (&acc)[4][4])
{
#pragma unroll 8
    for (int kk = 0; kk < 64; kk++) {
        float4 b4 = *reinterpret_cast<const float4*>(B + kk * bld + tc * 4);
        float a[4] = { A[kk * ald + tr], A[kk * ald + tr + 16],
                       A[kk * ald + tr + 32], A[kk * ald + tr + 48] };
        float bb[4] = { b4.x, b4.y, b4.z, b4.w };
#pragma unroll
        for (int i = 0; i < 4; i++)
#pragma unroll
            for (int j = 0; j < 4; j++) acc[i][j] = fmaf(a[i], bb[j], acc[i][j]);
    }
}

__device__ __forceinline__ void stage64c(float* dst, const float* __restrict__ src,
                                         int sld, int tid)
{
    for (int i = tid; i < 1024; i += 256) {
        int r = i >> 4, c4 = (i & 15) * 4;
        *reinterpret_cast<float4*>(dst + r * PL + c4) =
            *reinterpret_cast<const float4*>(src + r * sld + c4);
    }
}

__device__ __forceinline__ void ln64(const float* src, float* dst,
                                     const float* __restrict__ gg, const float* __restrict__ bb,
                                     int warp, int lane)
{
#pragma unroll 1
    for (int q = 0; q < 8; q++) {
        int s = warp * 8 + q;
        float v0 = src[s * PL + lane], v1 = src[s * PL + lane + 32];
        float s1 = v0 + v1, s2 = v0 * v0 + v1 * v1;
#pragma unroll
        for (int o = 16; o > 0; o >>= 1) {
            s1 += __shfl_xor_sync(~0u, s1, o);
            s2 += __shfl_xor_sync(~0u, s2, o);
        }
        float m = s1 * (1.0f / 64.0f);
        float r = rsqrtf(fmaxf(s2 * (1.0f / 64.0f) - m * m, 0.0f) + 1e-5f);
        dst[s * PL + lane]      = (v0 - m) * r * gg[lane] + bb[lane];
        dst[s * PL + lane + 32] = (v1 - m) * r * gg[lane + 32] + bb[lane + 32];
    }
}

// ============================ K0: tf32-round + fragment-permute all B weights ============================
extern "C" __global__ void k0(const float* __restrict__ Wsh, const float* __restrict__ Wasn,
                              const float* __restrict__ Win, const float* __restrict__ Wout)
{
    int i = blockIdx.x * 256 + threadIdx.x;
    if (i < 16384) {              // Wsh 256x64 -> 4 chunks (kt)
        int kf = i >> 6, c = i & 63;
        g_WshP[(kf >> 6) * 4096 + pidx(kf & 63, c)] = totf(Wsh[i]);
    }
    if (i < 8192) {               // Wasn 128x64 -> 2 chunks
        int kf = i >> 6, c = i & 63;
        g_WasnP[(kf >> 6) * 4096 + pidx(kf & 63, c)] = totf(Wasn[i]);
    }
    if (i < 32768) {              // Win 256x128 -> 8 chunks (kt*2+h)
        int kf = i >> 7, cf = i & 127;
        g_WinP[((kf >> 6) * 2 + (cf >> 6)) * 4096 + pidx(kf & 63, cf & 63)] = totf(Win[i]);
    }
    if (i < 16384) {              // Wout 64x256 -> 4 chunks (cc)
        int k = i >> 8, cf = i & 255;
        g_WoutP[(cf >> 6) * 4096 + pidx(k, cf & 63)] = totf(Wout[i]);
    }
}

// ============================ K1: phase 1 (tf32 mma, B from gmem) ============================
extern "C" __global__ void __launch_bounds__(256, 2)
k1(const float* __restrict__ xg, const float* __restrict__ geo,
   const float* __restrict__ g1, const float* __restrict__ b1,
   const float* __restrict__ bsh, const float* __restrict__ basn)
{
    extern __shared__ float sm[];
    float* sX   = sm;                 // 64 x PH  (full normalized x, tf32); sLg aliases
    float* sSh  = sX + 64 * PH;       // 64 x PL  (shared, tf32)
    float* sGeo = sSh + 64 * PL;      // 64 x PL  (geo, tf32)
    float* sG1  = sGeo + 64 * PL;     // 256
    float* sB1  = sG1 + 256;          // 256
    float* sMean = sB1 + 256;         // 64
    float* sRstd = sMean + 64;        // 64
    float* sBsh = sRstd + 64;         // 64
    float* sBa  = sBsh + 64;          // 64
    float* sLg  = sX;                 // alias (pitch PL), valid after GEMM1 done

    const int tid = threadIdx.x;
    const int tr = tid >> 4, tc = tid & 15;
    const int warp = tid >> 5, lane = tid & 31;
    const int wr = warp >> 1, wc = warp & 1;
    const int g = lane >> 2, q = lane & 3;
    const int b = blockIdx.x / BPB, rb = blockIdx.x % BPB;

    sG1[tid] = g1[tid]; sB1[tid] = b1[tid];
    if (tid < 64) { sBsh[tid] = bsh[tid]; sBa[tid] = basn[tid]; }
    float wloc = 0.0f;
    float Macc[4][4] = {};
    __syncthreads();

    for (int tile = rb; tile < NTILE; tile += BPB) {
        const size_t tok0 = (size_t)b * NTOK + (size_t)tile * TT;
        __syncthreads();   // prev tile readers of sLg/sSh/sGeo done

        // LN stats
#pragma unroll 1
        for (int qq = 0; qq < 8; qq++) {
            int t = warp * 8 + qq;
            const float* row = xg + (tok0 + t) * CD;
            float s1 = 0.0f, s2 = 0.0f;
#pragma unroll
            for (int k = 0; k < 8; k++) { float v = row[lane + 32 * k]; s1 += v; s2 += v * v; }
#pragma unroll
            for (int o = 16; o > 0; o >>= 1) {
                s1 += __shfl_xor_sync(~0u, s1, o);
                s2 += __shfl_xor_sync(~0u, s2, o);
            }
            if (lane == 0) {
                float m = s1 * (1.0f / 256.0f);
                sMean[t] = m;
                sRstd[t] = rsqrtf(fmaxf(s2 * (1.0f / 256.0f) - m * m, 0.0f) + 1e-5f);
            }
        }
        // geo -> sGeo (tf32)
        for (int i = tid; i < 1024; i += 256) {
            int t = i >> 4, c4 = (i & 15) * 4;
            float4 v = *reinterpret_cast<const float4*>(geo + (tok0 + t) * LD + c4);
            *reinterpret_cast<float4*>(sGeo + t * PL + c4) =
                make_float4(totf(v.x), totf(v.y), totf(v.z), totf(v.w));
        }
        __syncthreads();   // stats visible

        // full normalized x -> sX (tf32)
#pragma unroll
        for (int ii = 0; ii < 16; ii++) {
            int idx = tid + ii * 256;              // 0..4095 float4s
            int r = idx >> 6, c4 = (idx & 63) * 4;
            float4 xv = *reinterpret_cast<const float4*>(xg + (tok0 + r) * CD + c4);
            float m = sMean[r], rs = sRstd[r];
            *reinterpret_cast<float4*>(sX + r * PH + c4) = make_float4(
                totf((xv.x - m) * rs * sG1[c4 + 0] + sB1[c4 + 0]),
                totf((xv.y - m) * rs * sG1[c4 + 1] + sB1[c4 + 1]),
                totf((xv.z - m) * rs * sG1[c4 + 2] + sB1[c4 + 2]),
                totf((xv.w - m) * rs * sG1[c4 + 3] + sB1[c4 + 3]));
        }
        __syncthreads();   // sX visible

        // GEMM1: shared = LN(x) @ Wsh   (B fragments from gmem, no syncs)
        float a1[4][4] = {};
#pragma unroll 1
        for (int kt = 0; kt < 4; kt++)
            mma_gB(sX + kt * 64, PH, g_WshP + kt * 4096, wr, wc, g, q, a1);
        // shared -> sSh (tf32 + bias), own cells
#pragma unroll
        for (int t = 0; t < 4; t++) {
            int col = wc * 32 + t * 8 + 2 * q;
            int r0 = (wr * 16 + g) * PL, r1 = r0 + 8 * PL;
            sSh[r0 + col]     = totf(a1[t][0] + sBsh[col]);
            sSh[r0 + col + 1] = totf(a1[t][1] + sBsh[col + 1]);
            sSh[r1 + col]     = totf(a1[t][2] + sBsh[col]);
            sSh[r1 + col + 1] = totf(a1[t][3] + sBsh[col + 1]);
        }
        __syncthreads();   // sSh visible; sX reads (GEMM1) done -> sLg alias safe

        // GEMM3: logits = shared@Wasn0 + geo@Wasn1
        float a3[4][4] = {};
        mma_gB(sSh, PL, g_WasnP, wr, wc, g, q, a3);
        mma_gB(sGeo, PL, g_WasnP + 4096, wr, wc, g, q, a3);
#pragma unroll
        for (int t = 0; t < 4; t++) {
            int col = wc * 32 + t * 8 + 2 * q;
            int r0 = (wr * 16 + g) * PL, r1 = r0 + 8 * PL;
            sLg[r0 + col]     = a3[t][0] + sBa[col];
            sLg[r0 + col + 1] = a3[t][1] + sBa[col + 1];
            sLg[r1 + col]     = a3[t][2] + sBa[col];
            sLg[r1 + col + 1] = a3[t][3] + sBa[col + 1];
        }
        __syncthreads();   // logits visible

        // softmax -> w (fp32 in sLg, tf32 spill)
#pragma unroll 1
        for (int qq = 0; qq < 8; qq++) {
            int t = warp * 8 + qq;
            float v0 = sLg[t * PL + lane], v1 = sLg[t * PL + lane + 32];
            float mx = fmaxf(v0, v1);
#pragma unroll
            for (int o = 16; o > 0; o >>= 1) mx = fmaxf(mx, __shfl_xor_sync(~0u, mx, o));
            float e0 = __expf(v0 - mx), e1 = __expf(v1 - mx), ss = e0 + e1;
#pragma unroll
            for (int o = 16; o > 0; o >>= 1) ss += __shfl_xor_sync(~0u, ss, o);
            float inv = 1.0f / ss;
            float w0 = e0 * inv, w1 = e1 * inv;
            sLg[t * PL + lane] = w0; sLg[t * PL + lane + 32] = w1;
            float* wo = g_w + (tok0 + t) * SD;
            wo[lane] = totf(w0); wo[lane + 32] = totf(w1);
        }
        __syncthreads();

        if (tid < 64) {
            float cs = 0.0f;
            for (int t = 0; t < 64; t++) cs += sLg[t * PL + tid];
            wloc += cs;
        }
        // GEMM4': Macc += w^T @ shared (scalar fp32)
        mmT64(sLg, PL, sSh, PL, tr, tc, Macc);
    }

    if (tid < 64) atomicAdd(&g_wsum[b * 64 + tid], wloc);
#pragma unroll
    for (int i = 0; i < 4; i++)
#pragma unroll
        for (int j = 0; j < 4; j++)
            atomicAdd(&g_M[b * 4096 + (tr + 16 * i) * 64 + tc * 4 + j], Macc[i][j]);
}

// ============================ K2: slice reconstruction + latent transition ============================
extern "C" __global__ void __launch_bounds__(256, 1)
k2(const float* __restrict__ Wfe, const float* __restrict__ bfe,
   const float* __restrict__ Wd, const float* __restrict__ bd,
   const float* __restrict__ gdn, const float* __restrict__ bdn,
   const float* __restrict__ Wanc, const float* __restrict__ banc,
   const float* __restrict__ Wself, const float* __restrict__ Wctx,
   const float* __restrict__ gon, const float* __restrict__ bon,
   const float* __restrict__ Wup, const float* __restrict__ bup)
{
    extern __shared__ float sm[];
    float* sS  = sm;               // 64 x PH
    float* sWb = sS + 64 * PH;     // 256 x PL
    float* sT1 = sWb + 256 * PL;   // 64 x PL
    float* sT2 = sT1 + 64 * PL;    // 64 x PL
    float* sCx = sT2 + 64 * PL;    // 64 x PL
    float* sAn = sCx + 64 * PL;    // 16 x PL
    float* sAw = sAn + 16 * PL;    // 64 x 20
    float* sAs = sAw + 64 * 20;    // 16
    float* sWm = sAs + 16;         // 64

    const int tid = threadIdx.x;
    const int tr = tid >> 4, tc = tid & 15;
    const int warp = tid >> 5, lane = tid & 31;
    const int b = blockIdx.x;

    if (tid < 64) sWm[tid] = fmaxf(g_wsum[b * 64 + tid], 1e-6f);
    for (int i = tid; i < 64 * 64; i += 256) {
        int s = i >> 6, l = i & 63;
        sT1[s * PL + l] = g_M[b * 4096 + i];
    }
    __syncthreads();

    for (int cc = 0; cc < 4; cc++) {
        __syncthreads();
        stage64c(sWb, Wfe + cc * 64, 256, tid);
        __syncthreads();
        float acc[4][4] = {};
        mm64(sT1, PL, sWb, PL, tr, tc, acc);
#pragma unroll
        for (int i = 0; i < 4; i++)
#pragma unroll
            for (int j = 0; j < 4; j++) {
                int s = tr + 16 * i, c = cc * 64 + tc * 4 + j;
                float ws = sWm[s];
                sS[s * PH + c] = (acc[i][j] + ws * bfe[c]) / ws;
            }
    }
    __syncthreads();

    for (int i = tid; i < 256 * 16; i += 256) {
        int r = i >> 4, c4 = (i & 15) * 4;
        *reinterpret_cast<float4*>(sWb + r * PL + c4) =
            *reinterpret_cast<const float4*>(Wd + r * 64 + c4);
    }
    __syncthreads();
    {
        float acc[4][4] = {};
        for (int kt = 0; kt < 4; kt++)
            mm64(sS + kt * 64, PH, sWb + kt * 64 * PL, PL, tr, tc, acc);
        __syncthreads();
#pragma unroll
        for (int i = 0; i < 4; i++)
#pragma unroll
            for (int j = 0; j < 4; j++) {
                int c = tc * 4 + j;
                sT2[(tr + 16 * i) * PL + c] = acc[i][j] + bd[c];
            }
    }
    __syncthreads();
    ln64(sT2, sT1, gdn, bdn, warp, lane);
    __syncthreads();

    {
        int s = tid >> 2, a0 = (tid & 3) * 4;
        float a4[4] = {0.f, 0.f, 0.f, 0.f};
        for (int k = 0; k < 64; k++) {
            float av = sT1[s * PL + k];
#pragma unroll
            for (int j = 0; j < 4; j++) a4[j] = fmaf(av, Wanc[k * 16 + a0 + j], a4[j]);
        }
#pragma unroll
        for (int j = 0; j < 4; j++) sAw[s * 20 + a0 + j] = a4[j] + banc[a0 + j];
    }
    __syncthreads();
    if (tid < 64) {
        float mx = -1e30f;
        for (int a = 0; a < 16; a++) mx = fmaxf(mx, sAw[tid * 20 + a]);
        float e[16], ss = 0.0f;
        for (int a = 0; a < 16; a++) { e[a] = __expf(sAw[tid * 20 + a] - mx); ss += e[a]; }
        float inv = 1.0f / ss;
        for (int a = 0; a < 16; a++) sAw[tid * 20 + a] = e[a] * inv;
    }
    __syncthreads();
    if (tid < 16) {
        float cs = 0.0f;
        for (int s = 0; s < 64; s++) cs += sAw[s * 20 + tid];
        sAs[tid] = fmaxf(cs, 1e-6f);
    }
    __syncthreads();
    for (int idx = tid; idx < 16 * 64; idx += 256) {
        int a = idx >> 6, d = idx & 63;
        float s = 0.0f;
        for (int t = 0; t < 64; t++) s = fmaf(sAw[t * 20 + a], sT1[t * PL + d], s);
        sAn[a * PL + d] = s / sAs[a];
    }
    __syncthreads();
    for (int idx = tid; idx < 64 * 64; idx += 256) {
        int s = idx >> 6, d = idx & 63;
        float v = 0.0f;
#pragma unroll
        for (int a = 0; a < 16; a++) v = fmaf(sAw[s * 20 + a], sAn[a * PL + d], v);
        sCx[s * PL + d] = v;
    }
    __syncthreads();

    {
        float acc[4][4] = {};
        for (int i = tid; i < 64 * 16; i += 256) {
            int r = i >> 4, c4 = (i & 15) * 4;
            *reinterpret_cast<float4*>(sWb + r * PL + c4) =
                *reinterpret_cast<const float4*>(Wself + r * 64 + c4);
        }
        __syncthreads();
        mm64(sT1, PL, sWb, PL, tr, tc, acc);
        __syncthreads();
        for (int i = tid; i < 64 * 16; i += 256) {
            int r = i >> 4, c4 = (i & 15) * 4;
            *reinterpret_cast<float4*>(sWb + r * PL + c4) =
                *reinterpret_cast<const float4*>(Wctx + r * 64 + c4);
        }
        __syncthreads();
        mm64(sCx, PL, sWb, PL, tr, tc, acc);
#pragma unroll
        for (int i = 0; i < 4; i++)
#pragma unroll
            for (int j = 0; j < 4; j++) {
                int row = tr + 16 * i, c = tc * 4 + j;
                sT2[row * PL + c] = sT1[row * PL + c] + geluf(acc[i][j]);
            }
    }
    __syncthreads();
    ln64(sT2, sCx, gon, bon, warp, lane);
    __syncthreads();

    // st = LN(ul)@Wup + bup  (tf32, fragment-permuted into g_stP)
    for (int cc = 0; cc < 4; cc++) {
        __syncthreads();
        for (int i = tid; i < 64 * 16; i += 256) {
            int r = i >> 4, c4 = (i & 15) * 4;
            *reinterpret_cast<float4*>(sWb + r * PL + c4) =
                *reinterpret_cast<const float4*>(Wup + r * 256 + cc * 64 + c4);
        }
        __syncthreads();
        float acc[4][4] = {};
        mm64(sCx, PL, sWb, PL, tr, tc, acc);
#pragma unroll
        for (int i = 0; i < 4; i++)
#pragma unroll
            for (int j = 0; j < 4; j++) {
                int s = tr + 16 * i, cl = tc * 4 + j;
                g_stP[b * 16384 + cc * 4096 + pidx(s, cl)] = totf(acc[i][j] + bup[cc * 64 + cl]);
            }
    }
}

// ============================ K3: reader + channel mixer (mma, B from gmem) ============================
extern "C" __global__ void __launch_bounds__(256, 2)
k3(const float* __restrict__ xg,
   const float* __restrict__ g2, const float* __restrict__ b2,
   const float* __restrict__ binp, const float* __restrict__ boutp,
   float* __restrict__ out)
{
    extern __shared__ float sm[];
    float* sH  = sm;               // 64 x PH : LN2(y), tf32
    float* sWt = sH + 64 * PH;     // 64 x PL : w tile -> act
    float* sG2 = sWt + 64 * PL;    // 256
    float* sB2 = sG2 + 256;        // 256
    float* sBi = sB2 + 256;        // 128

    const int tid = threadIdx.x;
    const int warp = tid >> 5, lane = tid & 31;
    const int wr = warp >> 1, wc = warp & 1;
    const int g = lane >> 2, q = lane & 3;
    const int b = blockIdx.x / BPB, rb = blockIdx.x % BPB;

    sG2[tid] = g2[tid]; sB2[tid] = b2[tid];
    if (tid < 128) sBi[tid] = binp[tid];
    __syncthreads();

    for (int tile = rb; tile < NTILE; tile += BPB) {
        const size_t tok0 = (size_t)b * NTOK + (size_t)tile * TT;
        __syncthreads();   // prev tile: GEMM C reads of sWt + LN2 reads done

        // w tile (tf32) -> sWt
        for (int i = tid; i < 1024; i += 256) {
            int t = i >> 4, c4 = (i & 15) * 4;
            *reinterpret_cast<float4*>(sWt + t * PL + c4) =
                *reinterpret_cast<const float4*>(g_w + (tok0 + t) * SD + c4);
        }
        __syncthreads();   // sWt visible

        // GEMM A: y = x + w@st (st fragments from gmem, no inner syncs)
#pragma unroll 1
        for (int cc = 0; cc < 4; cc++) {
            float acc[4][4] = {};
            mma_gB(sWt, PL, g_stP + b * 16384 + cc * 4096, wr, wc, g, q, acc);
#pragma unroll
            for (int t = 0; t < 4; t++) {
                int col = cc * 64 + wc * 32 + t * 8 + 2 * q;
                size_t r0 = (tok0 + wr * 16 + g) * CD + col;
                size_t r1 = r0 + 8 * CD;
                float2 x0 = *reinterpret_cast<const float2*>(xg + r0);
                float2 x1 = *reinterpret_cast<const float2*>(xg + r1);
                *reinterpret_cast<float2*>(out + r0) = make_float2(acc[t][0] + x0.x, acc[t][1] + x0.y);
                *reinterpret_cast<float2*>(out + r1) = make_float2(acc[t][2] + x1.x, acc[t][3] + x1.y);
            }
        }
        __syncthreads();   // y visible CTA-wide; sWt reads done

        // LN2: y (from out) -> h (tf32) in sH
#pragma unroll 1
        for (int qq = 0; qq < 8; qq++) {
            int t = warp * 8 + qq;
            const float* yrow = out + (tok0 + t) * CD;
            float v[8], s1 = 0.0f, s2 = 0.0f;
#pragma unroll
            for (int k = 0; k < 8; k++) { v[k] = yrow[lane + 32 * k]; s1 += v[k]; s2 += v[k] * v[k]; }
#pragma unroll
            for (int o = 16; o > 0; o >>= 1) {
                s1 += __shfl_xor_sync(~0u, s1, o);
                s2 += __shfl_xor_sync(~0u, s2, o);
            }
            float m = s1 * (1.0f / 256.0f);
            float r = rsqrtf(fmaxf(s2 * (1.0f / 256.0f) - m * m, 0.0f) + 1e-5f);
#pragma unroll
            for (int k = 0; k < 8; k++) {
                int c = lane + 32 * k;
                sH[t * PH + c] = totf((v[k] - m) * r * sG2[c] + sB2[c]);
            }
        }
        __syncthreads();   // sH visible

        // GEMM B: vg = h @ Win (all B fragments from gmem, no syncs)
        float accv[4][4] = {}, accg[4][4] = {};
#pragma unroll 1
        for (int kt = 0; kt < 4; kt++) {
            mma_gB(sH + kt * 64, PH, g_WinP + (kt * 2) * 4096, wr, wc, g, q, accv);
            mma_gB(sH + kt * 64, PH, g_WinP + (kt * 2 + 1) * 4096, wr, wc, g, q, accg);
        }

        // act -> sWt (tf32)
#pragma unroll
        for (int t = 0; t < 4; t++) {
            int col = wc * 32 + t * 8 + 2 * q;
            int s0 = (wr * 16 + g) * PL + col;
            int s1 = s0 + 8 * PL;
            sWt[s0]     = totf(geluf(accv[t][0] + sBi[col])     * sigm(accg[t][0] + sBi[64 + col]));
            sWt[s0 + 1] = totf(geluf(accv[t][1] + sBi[col + 1]) * sigm(accg[t][1] + sBi[64 + col + 1]));
            sWt[s1]     = totf(geluf(accv[t][2] + sBi[col])     * sigm(accg[t][2] + sBi[64 + col]));
            sWt[s1 + 1] = totf(geluf(accv[t][3] + sBi[col + 1]) * sigm(accg[t][3] + sBi[64 + col + 1]));
        }
        __syncthreads();   // act visible

        // GEMM C: out = y + act @ Wout + bout
#pragma unroll 1
        for (int cc = 0; cc < 4; cc++) {
            float acc[4][4] = {};
            mma_gB(sWt, PL, g_WoutP + cc * 4096, wr, wc, g, q, acc);
#pragma unroll
            for (int t = 0; t < 4; t++) {
                int col = cc * 64 + wc * 32 + t * 8 + 2 * q;
                size_t r0 = (tok0 + wr * 16 + g) * CD + col;
                size_t r1 = r0 + 8 * CD;
                float2 y0 = *reinterpret_cast<const float2*>(out + r0);
                float2 y1 = *reinterpret_cast<const float2*>(out + r1);
                float2 bo = *reinterpret_cast<const float2*>(boutp + col);
                *reinterpret_cast<float2*>(out + r0) =
                    make_float2(y0.x + acc[t][0] + bo.x, y0.y + acc[t][1] + bo.y);
                *reinterpret_cast<float2*>(out + r1) =
                    make_float2(y1.x + acc[t][2] + bo.x, y1.y + acc[t][3] + bo.y);
            }
        }
    }
}

// ============================ launcher ============================
extern "C" void kernel_launch(void* const* d_in, const int* in_sizes, int n_in,
                              void* d_out, int out_size)
{
    const float* x     = (const float*)d_in[0];
    const float* geo   = (const float*)d_in[1];
    const float* ln1g  = (const float*)d_in[2];
    const float* ln1b  = (const float*)d_in[3];
    const float* Wsh   = (const float*)d_in[4];
    const float* bsh   = (const float*)d_in[5];
    const float* Wfe   = (const float*)d_in[6];
    const float* bfe   = (const float*)d_in[7];
    const float* Wasn  = (const float*)d_in[8];
    const float* basn  = (const float*)d_in[9];
    const float* Wd    = (const float*)d_in[10];
    const float* bd    = (const float*)d_in[11];
    const float* gdn   = (const float*)d_in[12];
    const float* bdn   = (const float*)d_in[13];
    const float* Wanc  = (const float*)d_in[14];
    const float* banc  = (const float*)d_in[15];
    const float* Wself = (const float*)d_in[16];
    const float* Wctx  = (const float*)d_in[17];
    const float* gon   = (const float*)d_in[18];
    const float* bon   = (const float*)d_in[19];
    const float* Wup   = (const float*)d_in[20];
    const float* bup   = (const float*)d_in[21];
    const float* ln2g  = (const float*)d_in[22];
    const float* ln2b  = (const float*)d_in[23];
    const float* Win   = (const float*)d_in[24];
    const float* binp  = (const float*)d_in[25];
    const float* Wout  = (const float*)d_in[26];
    const float* boutp = (const float*)d_in[27];
    float* out = (float*)d_out;

    const size_t S1 = (size_t)(64 * PH + 2 * 64 * PL + 2 * 256 + 4 * 64) * sizeof(float);
    const size_t S2 = (size_t)(64 * PH + 256 * PL + 3 * 64 * PL + 16 * PL + 64 * 20 + 16 + 64) * sizeof(float);
    const size_t S3 = (size_t)(64 * PH + 64 * PL + 2 * 256 + 128) * sizeof(float);

    cudaFuncSetAttribute(k1, cudaFuncAttributeMaxDynamicSharedMemorySize, (int)S1);
    cudaFuncSetAttribute(k2, cudaFuncAttributeMaxDynamicSharedMemorySize, (int)S2);
    cudaFuncSetAttribute(k3, cudaFuncAttributeMaxDynamicSharedMemorySize, (int)S3);

    void* pM = nullptr; void* pwsum = nullptr;
    cudaGetSymbolAddress(&pM, g_M);
    cudaGetSymbolAddress(&pwsum, g_wsum);
    cudaMemsetAsync(pM, 0, (size_t)NB * SD * LD * sizeof(float), 0);
    cudaMemsetAsync(pwsum, 0, (size_t)NB * SD * sizeof(float), 0);

    k0<<<128, 256>>>(Wsh, Wasn, Win, Wout);
    k1<<<NB * BPB, 256, S1>>>(x, geo, ln1g, ln1b, bsh, basn);
    k2<<<NB, 256, S2>>>(Wfe, bfe, Wd, bd, gdn, bdn, Wanc, banc, Wself, Wctx, gon, bon, Wup, bup);
    k3<<<NB * BPB, 256, S3>>>(x, ln2g, ln2b, binp, boutp, out);
}

// round 13
// speedup vs baseline: 1.1175x; 1.1175x over previous
#include <cuda_runtime.h>
#include <math.h>

#define NB   4
#define NTOK 65536
#define CD   256
#define LD   64
#define SD   64
#define TT   64
#define BPB  74
#define NTILE 1024
#define PH 260
#define PL 68

__device__ float g_w[(size_t)NB * NTOK * SD];   // softmax weights (tf32)
__device__ float g_M[NB * SD * LD];
__device__ float g_wsum[NB * SD];
__device__ float g_st[NB * SD * CD];            // st (tf32, row-major)
__device__ float g_WshT[CD * LD];               // tf32 Wsh
__device__ float g_WasnT[2 * LD * SD];          // tf32 Wasn (128x64)
__device__ float g_WinT[CD * 128];              // tf32 Win
__device__ float g_WoutT[LD * CD];              // tf32 Wout

__device__ __forceinline__ float geluf(float x) {
    return 0.5f * x * (1.0f + erff(x * 0.70710678118654752f));
}
__device__ __forceinline__ float sigm(float x) { return 1.0f / (1.0f + __expf(-x)); }

__device__ __forceinline__ float totf(float x) {
    unsigned r;
    asm("cvt.rna.tf32.f32 %0, %1;" : "=r"(r) : "f"(x));
    return __uint_as_float(r);
}

__device__ __forceinline__ void mma8(float (&d)[4], const unsigned (&a)[4], const unsigned (&b)[2]) {
    asm volatile("mma.sync.aligned.m16n8k8.row.col.f32.tf32.tf32.f32 "
                 "{%0,%1,%2,%3}, {%4,%5,%6,%7}, {%8,%9}, {%0,%1,%2,%3};"
                 : "+f"(d[0]), "+f"(d[1]), "+f"(d[2]), "+f"(d[3])
                 : "r"(a[0]), "r"(a[1]), "r"(a[2]), "r"(a[3]), "r"(b[0]), "r"(b[1]));
}

// warp mma: acc(16x32) += A(64 rows x 64 k, smem pitch lda) @ B(64x64 smem chunk, pitch PL)
__device__ __forceinline__ void mma_warp64(const float* __restrict__ sA, int lda,
                                           const float* __restrict__ sB,
                                           int wr, int wc, int g, int q, float (&acc)[4][4])
{
#pragma unroll
    for (int k8 = 0; k8 < 64; k8 += 8) {
        const float* Ab = sA + (wr * 16 + g) * lda + k8 + q;
        unsigned a[4] = { __float_as_uint(Ab[0]), __float_as_uint(Ab[8 * lda]),
                          __float_as_uint(Ab[4]), __float_as_uint(Ab[8 * lda + 4]) };
#pragma unroll
        for (int t = 0; t < 4; t++) {
            const float* Bb = sB + (k8 + q) * PL + wc * 32 + t * 8 + g;
            unsigned b[2] = { __float_as_uint(Bb[0]), __float_as_uint(Bb[4 * PL]) };
            mma8(acc[t], a, b);
        }
    }
}

// ---------- cp.async staging (16B granules) into pitch-PL smem ----------
__device__ __forceinline__ void cp_stage(float* dst, const float* __restrict__ src,
                                         int sld, int tid)
{
    for (int i = tid; i < 1024; i += 256) {
        int r = i >> 4, c4 = (i & 15) * 4;
        unsigned ds = (unsigned)__cvta_generic_to_shared(dst + r * PL + c4);
        asm volatile("cp.async.cg.shared.global [%0], [%1], 16;"
                     :: "r"(ds), "l"(src + r * sld + c4) : "memory");
    }
}
#define CP_COMMIT() asm volatile("cp.async.commit_group;" ::: "memory")
#define CP_WAIT(n)  asm volatile("cp.async.wait_group %0;" :: "n"(n) : "memory")

// ---------- scalar micro-kernels (k2 + k1's GEMM4') ----------
__device__ __forceinline__ void mm64(const float* __restrict__ A, int ald,
                                     const float* __restrict__ B, int bld,
                                     int tr, int tc, float (&acc)[4][4])
{
#pragma unroll 8
    for (int kk = 0; kk < 64; kk++) {
        float4 b4 = *reinterpret_cast<const float4*>(B + kk * bld + tc * 4);
        float a[4] = { A[tr * ald + kk], A[(tr + 16) * ald + kk],
                       A[(tr + 32) * ald + kk], A[(tr + 48) * ald + kk] };
        float bb[4] = { b4.x, b4.y, b4.z, b4.w };
#pragma unroll
        for (int i = 0; i < 4; i++)
#pragma unroll
            for (int j = 0; j < 4; j++) acc[i][j] = fmaf(a[i], bb[j], acc[i][j]);
    }
}

__device__ __forceinline__ void mmT64(const float* __restrict__ A, int ald,
                                      const float* __restrict__ B, int bld,
                                      int tr, int tc, float (&acc)[4][4])
{
#pragma unroll 8
    for (int kk = 0; kk < 64; kk++) {
        float4 b4 = *reinterpret_cast<const float4*>(B + kk * bld + tc * 4);
        float a[4] = { A[kk * ald + tr], A[kk * ald + tr + 16],
                       A[kk * ald + tr + 32], A[kk * ald + tr + 48] };
        float bb[4] = { b4.x, b4.y, b4.z, b4.w };
#pragma unroll
        for (int i = 0; i < 4; i++)
#pragma unroll
            for (int j = 0; j < 4; j++) acc[i][j] = fmaf(a[i], bb[j], acc[i][j]);
    }
}

__device__ __forceinline__ void stage64c(float* dst, const float* __restrict__ src,
                                         int sld, int tid)
{
    for (int i = tid; i < 1024; i += 256) {
        int r = i >> 4, c4 = (i & 15) * 4;
        *reinterpret_cast<float4*>(dst + r * PL + c4) =
            *reinterpret_cast<const float4*>(src + r * sld + c4);
    }
}

__device__ __forceinline__ void ln64(const float* src, float* dst,
                                     const float* __restrict__ gg, const float* __restrict__ bb,
                                     int warp, int lane)
{
#pragma unroll 1
    for (int q = 0; q < 8; q++) {
        int s = warp * 8 + q;
        float v0 = src[s * PL + lane], v1 = src[s * PL + lane + 32];
        float s1 = v0 + v1, s2 = v0 * v0 + v1 * v1;
#pragma unroll
        for (int o = 16; o > 0; o >>= 1) {
            s1 += __shfl_xor_sync(~0u, s1, o);
            s2 += __shfl_xor_sync(~0u, s2, o);
        }
        float m = s1 * (1.0f / 64.0f);
        float r = rsqrtf(fmaxf(s2 * (1.0f / 64.0f) - m * m, 0.0f) + 1e-5f);
        dst[s * PL + lane]      = (v0 - m) * r * gg[lane] + bb[lane];
        dst[s * PL + lane + 32] = (v1 - m) * r * gg[lane + 32] + bb[lane + 32];
    }
}

// ============================ K0: tf32-round all mma B weights ============================
extern "C" __global__ void k0(const float* __restrict__ Wsh, const float* __restrict__ Wasn,
                              const float* __restrict__ Win, const float* __restrict__ Wout)
{
    int i = blockIdx.x * 256 + threadIdx.x;
    if (i < CD * LD)     g_WshT[i] = totf(Wsh[i]);
    if (i < 2 * LD * SD) g_WasnT[i] = totf(Wasn[i]);
    if (i < CD * 128)    g_WinT[i] = totf(Win[i]);
    if (i < LD * CD)     g_WoutT[i] = totf(Wout[i]);
}

// ============================ K1: phase 1 (tf32 mma, cp.async pipelined) ============================
extern "C" __global__ void __launch_bounds__(256, 2)
k1(const float* __restrict__ xg, const float* __restrict__ geo,
   const float* __restrict__ g1, const float* __restrict__ b1,
   const float* __restrict__ bsh, const float* __restrict__ basn)
{
    extern __shared__ float sm[];
    float* sX   = sm;                 // 64 x PL  (normalized x chunk, tf32)
    float* sSh  = sX + 64 * PL;       // 64 x PL  (shared, tf32)
    float* sLg  = sSh + 64 * PL;      // 64 x PL  (logits -> w)
    float* sGeo = sLg + 64 * PL;      // 64 x PL  (geo, tf32)
    float* wb0  = sGeo + 64 * PL;     // 64 x PL  stage buffer 0
    float* wb1  = wb0 + 64 * PL;      // 64 x PL  stage buffer 1
    float* sG1  = wb1 + 64 * PL;      // 256
    float* sB1  = sG1 + 256;          // 256
    float* sMean = sB1 + 256;         // 64
    float* sRstd = sMean + 64;        // 64
    float* sBsh = sRstd + 64;         // 64
    float* sBa  = sBsh + 64;          // 64

    const int tid = threadIdx.x;
    const int tr = tid >> 4, tc = tid & 15;
    const int warp = tid >> 5, lane = tid & 31;
    const int wr = warp >> 1, wc = warp & 1;
    const int g = lane >> 2, q = lane & 3;
    const int b = blockIdx.x / BPB, rb = blockIdx.x % BPB;
    float* wb[2] = { wb0, wb1 };

    sG1[tid] = g1[tid]; sB1[tid] = b1[tid];
    if (tid < 64) { sBsh[tid] = bsh[tid]; sBa[tid] = basn[tid]; }
    float wloc = 0.0f;
    float Macc[4][4] = {};
    __syncthreads();

    for (int tile = rb; tile < NTILE; tile += BPB) {
        const size_t tok0 = (size_t)b * NTOK + (size_t)tile * TT;
        __syncthreads();   // prev tile readers of sLg/sSh/sGeo/sX/wb done

        // prefetch Wsh chunk 0
        cp_stage(wb0, g_WshT, 64, tid);
        CP_COMMIT();

        // LN stats
#pragma unroll 1
        for (int qq = 0; qq < 8; qq++) {
            int t = warp * 8 + qq;
            const float* row = xg + (tok0 + t) * CD;
            float s1 = 0.0f, s2 = 0.0f;
#pragma unroll
            for (int k = 0; k < 8; k++) { float v = row[lane + 32 * k]; s1 += v; s2 += v * v; }
#pragma unroll
            for (int o = 16; o > 0; o >>= 1) {
                s1 += __shfl_xor_sync(~0u, s1, o);
                s2 += __shfl_xor_sync(~0u, s2, o);
            }
            if (lane == 0) {
                float m = s1 * (1.0f / 256.0f);
                sMean[t] = m;
                sRstd[t] = rsqrtf(fmaxf(s2 * (1.0f / 256.0f) - m * m, 0.0f) + 1e-5f);
            }
        }
        // geo -> sGeo (tf32)
        for (int i = tid; i < 1024; i += 256) {
            int t = i >> 4, c4 = (i & 15) * 4;
            float4 v = *reinterpret_cast<const float4*>(geo + (tok0 + t) * LD + c4);
            *reinterpret_cast<float4*>(sGeo + t * PL + c4) =
                make_float4(totf(v.x), totf(v.y), totf(v.z), totf(v.w));
        }
        __syncthreads();   // stats visible

        // GEMM1 (pipelined): shared = LN(x) @ Wsh
        float a1[4][4] = {};
#pragma unroll 1
        for (int kt = 0; kt < 4; kt++) {
            const int base = kt * 64;
            // compute normalized x chunk -> sX (overlaps inflight cp.async)
#pragma unroll
            for (int ii = 0; ii < 4; ii++) {
                int idx = tid + ii * 256;
                int r = idx >> 4, c4 = (idx & 15) * 4;
                float4 xv = *reinterpret_cast<const float4*>(xg + (tok0 + r) * CD + base + c4);
                float m = sMean[r], rs = sRstd[r];
                *reinterpret_cast<float4*>(sX + r * PL + c4) = make_float4(
                    totf((xv.x - m) * rs * sG1[base + c4 + 0] + sB1[base + c4 + 0]),
                    totf((xv.y - m) * rs * sG1[base + c4 + 1] + sB1[base + c4 + 1]),
                    totf((xv.z - m) * rs * sG1[base + c4 + 2] + sB1[base + c4 + 2]),
                    totf((xv.w - m) * rs * sG1[base + c4 + 3] + sB1[base + c4 + 3]));
            }
            if (kt < 3) { cp_stage(wb[(kt + 1) & 1], g_WshT + (kt + 1) * 64 * 64, 64, tid); CP_COMMIT(); }
            if (kt < 3) { CP_WAIT(1); } else { CP_WAIT(0); }
            __syncthreads();
            mma_warp64(sX, PL, wb[kt & 1], wr, wc, g, q, a1);
            __syncthreads();
        }
        // shared -> sSh (tf32 + bias); prefetch both Wasn chunks
#pragma unroll
        for (int t = 0; t < 4; t++) {
            int col = wc * 32 + t * 8 + 2 * q;
            int r0 = (wr * 16 + g) * PL, r1 = r0 + 8 * PL;
            sSh[r0 + col]     = totf(a1[t][0] + sBsh[col]);
            sSh[r0 + col + 1] = totf(a1[t][1] + sBsh[col + 1]);
            sSh[r1 + col]     = totf(a1[t][2] + sBsh[col]);
            sSh[r1 + col + 1] = totf(a1[t][3] + sBsh[col + 1]);
        }
        cp_stage(wb0, g_WasnT, 64, tid);
        cp_stage(wb1, g_WasnT + 64 * 64, 64, tid);
        CP_COMMIT();
        CP_WAIT(0);
        __syncthreads();   // sSh + Wasn chunks visible

        // GEMM3: logits = shared@Wasn0 + geo@Wasn1
        float a3[4][4] = {};
        mma_warp64(sSh, PL, wb0, wr, wc, g, q, a3);
        mma_warp64(sGeo, PL, wb1, wr, wc, g, q, a3);
#pragma unroll
        for (int t = 0; t < 4; t++) {
            int col = wc * 32 + t * 8 + 2 * q;
            int r0 = (wr * 16 + g) * PL, r1 = r0 + 8 * PL;
            sLg[r0 + col]     = a3[t][0] + sBa[col];
            sLg[r0 + col + 1] = a3[t][1] + sBa[col + 1];
            sLg[r1 + col]     = a3[t][2] + sBa[col];
            sLg[r1 + col + 1] = a3[t][3] + sBa[col + 1];
        }
        __syncthreads();

        // softmax -> w (fp32 in sLg, tf32 spill)
#pragma unroll 1
        for (int qq = 0; qq < 8; qq++) {
            int t = warp * 8 + qq;
            float v0 = sLg[t * PL + lane], v1 = sLg[t * PL + lane + 32];
            float mx = fmaxf(v0, v1);
#pragma unroll
            for (int o = 16; o > 0; o >>= 1) mx = fmaxf(mx, __shfl_xor_sync(~0u, mx, o));
            float e0 = __expf(v0 - mx), e1 = __expf(v1 - mx), ss = e0 + e1;
#pragma unroll
            for (int o = 16; o > 0; o >>= 1) ss += __shfl_xor_sync(~0u, ss, o);
            float inv = 1.0f / ss;
            float w0 = e0 * inv, w1 = e1 * inv;
            sLg[t * PL + lane] = w0; sLg[t * PL + lane + 32] = w1;
            float* wo = g_w + (tok0 + t) * SD;
            wo[lane] = totf(w0); wo[lane + 32] = totf(w1);
        }
        __syncthreads();

        if (tid < 64) {
            float cs = 0.0f;
            for (int t = 0; t < 64; t++) cs += sLg[t * PL + tid];
            wloc += cs;
        }
        mmT64(sLg, PL, sSh, PL, tr, tc, Macc);
    }

    if (tid < 64) atomicAdd(&g_wsum[b * 64 + tid], wloc);
#pragma unroll
    for (int i = 0; i < 4; i++)
#pragma unroll
        for (int j = 0; j < 4; j++)
            atomicAdd(&g_M[b * 4096 + (tr + 16 * i) * 64 + tc * 4 + j], Macc[i][j]);
}

// ============================ K2: slice reconstruction + latent transition ============================
extern "C" __global__ void __launch_bounds__(256, 1)
k2(const float* __restrict__ Wfe, const float* __restrict__ bfe,
   const float* __restrict__ Wd, const float* __restrict__ bd,
   const float* __restrict__ gdn, const float* __restrict__ bdn,
   const float* __restrict__ Wanc, const float* __restrict__ banc,
   const float* __restrict__ Wself, const float* __restrict__ Wctx,
   const float* __restrict__ gon, const float* __restrict__ bon,
   const float* __restrict__ Wup, const float* __restrict__ bup)
{
    extern __shared__ float sm[];
    float* sS  = sm;               // 64 x PH
    float* sWb = sS + 64 * PH;     // 256 x PL
    float* sT1 = sWb + 256 * PL;   // 64 x PL
    float* sT2 = sT1 + 64 * PL;    // 64 x PL
    float* sCx = sT2 + 64 * PL;    // 64 x PL
    float* sAn = sCx + 64 * PL;    // 16 x PL
    float* sAw = sAn + 16 * PL;    // 64 x 20
    float* sAs = sAw + 64 * 20;    // 16
    float* sWm = sAs + 16;         // 64

    const int tid = threadIdx.x;
    const int tr = tid >> 4, tc = tid & 15;
    const int warp = tid >> 5, lane = tid & 31;
    const int b = blockIdx.x;

    if (tid < 64) sWm[tid] = fmaxf(g_wsum[b * 64 + tid], 1e-6f);
    for (int i = tid; i < 64 * 64; i += 256) {
        int s = i >> 6, l = i & 63;
        sT1[s * PL + l] = g_M[b * 4096 + i];
    }
    __syncthreads();

    for (int cc = 0; cc < 4; cc++) {
        __syncthreads();
        stage64c(sWb, Wfe + cc * 64, 256, tid);
        __syncthreads();
        float acc[4][4] = {};
        mm64(sT1, PL, sWb, PL, tr, tc, acc);
#pragma unroll
        for (int i = 0; i < 4; i++)
#pragma unroll
            for (int j = 0; j < 4; j++) {
                int s = tr + 16 * i, c = cc * 64 + tc * 4 + j;
                float ws = sWm[s];
                sS[s * PH + c] = (acc[i][j] + ws * bfe[c]) / ws;
            }
    }
    __syncthreads();

    for (int i = tid; i < 256 * 16; i += 256) {
        int r = i >> 4, c4 = (i & 15) * 4;
        *reinterpret_cast<float4*>(sWb + r * PL + c4) =
            *reinterpret_cast<const float4*>(Wd + r * 64 + c4);
    }
    __syncthreads();
    {
        float acc[4][4] = {};
        for (int kt = 0; kt < 4; kt++)
            mm64(sS + kt * 64, PH, sWb + kt * 64 * PL, PL, tr, tc, acc);
        __syncthreads();
#pragma unroll
        for (int i = 0; i < 4; i++)
#pragma unroll
            for (int j = 0; j < 4; j++) {
                int c = tc * 4 + j;
                sT2[(tr + 16 * i) * PL + c] = acc[i][j] + bd[c];
            }
    }
    __syncthreads();
    ln64(sT2, sT1, gdn, bdn, warp, lane);
    __syncthreads();

    {
        int s = tid >> 2, a0 = (tid & 3) * 4;
        float a4[4] = {0.f, 0.f, 0.f, 0.f};
        for (int k = 0; k < 64; k++) {
            float av = sT1[s * PL + k];
#pragma unroll
            for (int j = 0; j < 4; j++) a4[j] = fmaf(av, Wanc[k * 16 + a0 + j], a4[j]);
        }
#pragma unroll
        for (int j = 0; j < 4; j++) sAw[s * 20 + a0 + j] = a4[j] + banc[a0 + j];
    }
    __syncthreads();
    if (tid < 64) {
        float mx = -1e30f;
        for (int a = 0; a < 16; a++) mx = fmaxf(mx, sAw[tid * 20 + a]);
        float e[16], ss = 0.0f;
        for (int a = 0; a < 16; a++) { e[a] = __expf(sAw[tid * 20 + a] - mx); ss += e[a]; }
        float inv = 1.0f / ss;
        for (int a = 0; a < 16; a++) sAw[tid * 20 + a] = e[a] * inv;
    }
    __syncthreads();
    if (tid < 16) {
        float cs = 0.0f;
        for (int s = 0; s < 64; s++) cs += sAw[s * 20 + tid];
        sAs[tid] = fmaxf(cs, 1e-6f);
    }
    __syncthreads();
    for (int idx = tid; idx < 16 * 64; idx += 256) {
        int a = idx >> 6, d = idx & 63;
        float s = 0.0f;
        for (int t = 0; t < 64; t++) s = fmaf(sAw[t * 20 + a], sT1[t * PL + d], s);
        sAn[a * PL + d] = s / sAs[a];
    }
    __syncthreads();
    for (int idx = tid; idx < 64 * 64; idx += 256) {
        int s = idx >> 6, d = idx & 63;
        float v = 0.0f;
#pragma unroll
        for (int a = 0; a < 16; a++) v = fmaf(sAw[s * 20 + a], sAn[a * PL + d], v);
        sCx[s * PL + d] = v;
    }
    __syncthreads();

    {
        float acc[4][4] = {};
        for (int i = tid; i < 64 * 16; i += 256) {
            int r = i >> 4, c4 = (i & 15) * 4;
            *reinterpret_cast<float4*>(sWb + r * PL + c4) =
                *reinterpret_cast<const float4*>(Wself + r * 64 + c4);
        }
        __syncthreads();
        mm64(sT1, PL, sWb, PL, tr, tc, acc);
        __syncthreads();
        for (int i = tid; i < 64 * 16; i += 256) {
            int r = i >> 4, c4 = (i & 15) * 4;
            *reinterpret_cast<float4*>(sWb + r * PL + c4) =
                *reinterpret_cast<const float4*>(Wctx + r * 64 + c4);
        }
        __syncthreads();
        mm64(sCx, PL, sWb, PL, tr, tc, acc);
#pragma unroll
        for (int i = 0; i < 4; i++)
#pragma unroll
            for (int j = 0; j < 4; j++) {
                int row = tr + 16 * i, c = tc * 4 + j;
                sT2[row * PL + c] = sT1[row * PL + c] + geluf(acc[i][j]);
            }
    }
    __syncthreads();
    ln64(sT2, sCx, gon, bon, warp, lane);
    __syncthreads();

    // st = LN(ul)@Wup + bup (tf32, row-major)
    for (int cc = 0; cc < 4; cc++) {
        __syncthreads();
        for (int i = tid; i < 64 * 16; i += 256) {
            int r = i >> 4, c4 = (i & 15) * 4;
            *reinterpret_cast<float4*>(sWb + r * PL + c4) =
                *reinterpret_cast<const float4*>(Wup + r * 256 + cc * 64 + c4);
        }
        __syncthreads();
        float acc[4][4] = {};
        mm64(sCx, PL, sWb, PL, tr, tc, acc);
#pragma unroll
        for (int i = 0; i < 4; i++)
#pragma unroll
            for (int j = 0; j < 4; j++) {
                int row = tr + 16 * i, c = cc * 64 + tc * 4 + j;
                g_st[b * 16384 + row * 256 + c] = totf(acc[i][j] + bup[c]);
            }
    }
}

// ============================ K3a: y = x + w@st (pipelined, 3 CTAs/SM) ============================
extern "C" __global__ void __launch_bounds__(256, 3)
k3a(const float* __restrict__ xg, float* __restrict__ out)
{
    extern __shared__ float sm[];
    float* sWt = sm;               // 64 x PL : w tile (A)
    float* sb0 = sWt + 64 * PL;    // stage buffers
    float* sb1 = sb0 + 64 * PL;

    const int tid = threadIdx.x;
    const int warp = tid >> 5, lane = tid & 31;
    const int wr = warp >> 1, wc = warp & 1;
    const int g = lane >> 2, q = lane & 3;
    const int b = blockIdx.x / BPB, rb = blockIdx.x % BPB;
    float* sb[2] = { sb0, sb1 };

    for (int tile = rb; tile < NTILE; tile += BPB) {
        const size_t tok0 = (size_t)b * NTOK + (size_t)tile * TT;
        __syncthreads();   // prev tile readers done

        cp_stage(sWt, g_w + tok0 * SD, SD, tid);
        cp_stage(sb0, g_st + b * 16384, 256, tid);
        CP_COMMIT();

#pragma unroll 1
        for (int cc = 0; cc < 4; cc++) {
            if (cc < 3) { cp_stage(sb[(cc + 1) & 1], g_st + b * 16384 + (cc + 1) * 64, 256, tid); CP_COMMIT(); }
            if (cc < 3) { CP_WAIT(1); } else { CP_WAIT(0); }
            __syncthreads();
            float acc[4][4] = {};
            mma_warp64(sWt, PL, sb[cc & 1], wr, wc, g, q, acc);
#pragma unroll
            for (int t = 0; t < 4; t++) {
                int col = cc * 64 + wc * 32 + t * 8 + 2 * q;
                size_t r0 = (tok0 + wr * 16 + g) * CD + col;
                size_t r1 = r0 + 8 * CD;
                float2 x0 = *reinterpret_cast<const float2*>(xg + r0);
                float2 x1 = *reinterpret_cast<const float2*>(xg + r1);
                *reinterpret_cast<float2*>(out + r0) = make_float2(acc[t][0] + x0.x, acc[t][1] + x0.y);
                *reinterpret_cast<float2*>(out + r1) = make_float2(acc[t][2] + x1.x, acc[t][3] + x1.y);
            }
            __syncthreads();
        }
    }
}

// ============================ K3b: LN2 + GLU + out-proj (pipelined) ============================
extern "C" __global__ void __launch_bounds__(256, 2)
k3b(const float* __restrict__ g2, const float* __restrict__ b2,
    const float* __restrict__ binp, const float* __restrict__ boutp,
    float* __restrict__ out)
{
    extern __shared__ float sm[];
    float* sH  = sm;               // 64 x PH : LN2(y) tf32; first 64xPL reused for act
    float* bb0 = sH + 64 * PH;     // stage buffers
    float* bb1 = bb0 + 64 * PL;
    float* sG2 = bb1 + 64 * PL;    // 256
    float* sB2 = sG2 + 256;        // 256
    float* sBi = sB2 + 256;        // 128

    const int tid = threadIdx.x;
    const int warp = tid >> 5, lane = tid & 31;
    const int wr = warp >> 1, wc = warp & 1;
    const int g = lane >> 2, q = lane & 3;
    const int b = blockIdx.x / BPB, rb = blockIdx.x % BPB;
    float* bb[2] = { bb0, bb1 };
    float* sAct = sH;              // alias, pitch PL

    sG2[tid] = g2[tid]; sB2[tid] = b2[tid];
    if (tid < 128) sBi[tid] = binp[tid];
    __syncthreads();

    for (int tile = rb; tile < NTILE; tile += BPB) {
        const size_t tok0 = (size_t)b * NTOK + (size_t)tile * TT;
        __syncthreads();   // prev tile readers done

        cp_stage(bb0, g_WinT, 128, tid);   // Win chunk (kt=0, v-half)
        CP_COMMIT();

        // LN2: y (from out, written by k3a) -> h (tf32) in sH
#pragma unroll 1
        for (int qq = 0; qq < 8; qq++) {
            int t = warp * 8 + qq;
            const float* yrow = out + (tok0 + t) * CD;
            float v[8], s1 = 0.0f, s2 = 0.0f;
#pragma unroll
            for (int k = 0; k < 8; k++) { v[k] = yrow[lane + 32 * k]; s1 += v[k]; s2 += v[k] * v[k]; }
#pragma unroll
            for (int o = 16; o > 0; o >>= 1) {
                s1 += __shfl_xor_sync(~0u, s1, o);
                s2 += __shfl_xor_sync(~0u, s2, o);
            }
            float m = s1 * (1.0f / 256.0f);
            float r = rsqrtf(fmaxf(s2 * (1.0f / 256.0f) - m * m, 0.0f) + 1e-5f);
#pragma unroll
            for (int k = 0; k < 8; k++) {
                int c = lane + 32 * k;
                sH[t * PH + c] = totf((v[k] - m) * r * sG2[c] + sB2[c]);
            }
        }
        __syncthreads();   // sH visible (cp group 0 still inflight is fine)

        // GEMM B: vg = h @ Win   (8 chunks: c = kt*2 + h)
        float accv[4][4] = {}, accg[4][4] = {};
#pragma unroll 1
        for (int c = 0; c < 8; c++) {
            if (c < 7) {
                int nkt = (c + 1) >> 1, nh = (c + 1) & 1;
                cp_stage(bb[(c + 1) & 1], g_WinT + nkt * 64 * 128 + nh * 64, 128, tid);
                CP_COMMIT();
            }
            if (c < 7) { CP_WAIT(1); } else { CP_WAIT(0); }
            __syncthreads();
            if (c & 1) mma_warp64(sH + (c >> 1) * 64, PH, bb[c & 1], wr, wc, g, q, accg);
            else       mma_warp64(sH + (c >> 1) * 64, PH, bb[c & 1], wr, wc, g, q, accv);
            __syncthreads();
        }

        // prefetch Wout chunk 0 while computing act
        cp_stage(bb0, g_WoutT, 256, tid);
        CP_COMMIT();

        // act -> sAct (reuses sH start; GEMM B reads done)
#pragma unroll
        for (int t = 0; t < 4; t++) {
            int col = wc * 32 + t * 8 + 2 * q;
            int s0 = (wr * 16 + g) * PL + col;
            int s1 = s0 + 8 * PL;
            sAct[s0]     = totf(geluf(accv[t][0] + sBi[col])     * sigm(accg[t][0] + sBi[64 + col]));
            sAct[s0 + 1] = totf(geluf(accv[t][1] + sBi[col + 1]) * sigm(accg[t][1] + sBi[64 + col + 1]));
            sAct[s1]     = totf(geluf(accv[t][2] + sBi[col])     * sigm(accg[t][2] + sBi[64 + col]));
            sAct[s1 + 1] = totf(geluf(accv[t][3] + sBi[col + 1]) * sigm(accg[t][3] + sBi[64 + col + 1]));
        }

        // GEMM C: out = y + act @ Wout + bout
#pragma unroll 1
        for (int cc = 0; cc < 4; cc++) {
            if (cc < 3) { cp_stage(bb[(cc + 1) & 1], g_WoutT + (cc + 1) * 64, 256, tid); CP_COMMIT(); }
            if (cc < 3) { CP_WAIT(1); } else { CP_WAIT(0); }
            __syncthreads();   // act (cc=0) + staged chunk visible
            float acc[4][4] = {};
            mma_warp64(sAct, PL, bb[cc & 1], wr, wc, g, q, acc);
#pragma unroll
            for (int t = 0; t < 4; t++) {
                int col = cc * 64 + wc * 32 + t * 8 + 2 * q;
                size_t r0 = (tok0 + wr * 16 + g) * CD + col;
                size_t r1 = r0 + 8 * CD;
                float2 y0 = *reinterpret_cast<const float2*>(out + r0);
                float2 y1 = *reinterpret_cast<const float2*>(out + r1);
                float2 bo = *reinterpret_cast<const float2*>(boutp + col);
                *reinterpret_cast<float2*>(out + r0) =
                    make_float2(y0.x + acc[t][0] + bo.x, y0.y + acc[t][1] + bo.y);
                *reinterpret_cast<float2*>(out + r1) =
                    make_float2(y1.x + acc[t][2] + bo.x, y1.y + acc[t][3] + bo.y);
            }
            __syncthreads();
        }
    }
}

// ============================ launcher ============================
extern "C" void kernel_launch(void* const* d_in, const int* in_sizes, int n_in,
                              void* d_out, int out_size)
{
    const float* x     = (const float*)d_in[0];
    const float* geo   = (const float*)d_in[1];
    const float* ln1g  = (const float*)d_in[2];
    const float* ln1b  = (const float*)d_in[3];
    const float* Wsh   = (const float*)d_in[4];
    const float* bsh   = (const float*)d_in[5];
    const float* Wfe   = (const float*)d_in[6];
    const float* bfe   = (const float*)d_in[7];
    const float* Wasn  = (const float*)d_in[8];
    const float* basn  = (const float*)d_in[9];
    const float* Wd    = (const float*)d_in[10];
    const float* bd    = (const float*)d_in[11];
    const float* gdn   = (const float*)d_in[12];
    const float* bdn   = (const float*)d_in[13];
    const float* Wanc  = (const float*)d_in[14];
    const float* banc  = (const float*)d_in[15];
    const float* Wself = (const float*)d_in[16];
    const float* Wctx  = (const float*)d_in[17];
    const float* gon   = (const float*)d_in[18];
    const float* bon   = (const float*)d_in[19];
    const float* Wup   = (const float*)d_in[20];
    const float* bup   = (const float*)d_in[21];
    const float* ln2g  = (const float*)d_in[22];
    const float* ln2b  = (const float*)d_in[23];
    const float* Win   = (const float*)d_in[24];
    const float* binp  = (const float*)d_in[25];
    const float* Wout  = (const float*)d_in[26];
    const float* boutp = (const float*)d_in[27];
    float* out = (float*)d_out;

    const size_t S1  = (size_t)(6 * 64 * PL + 2 * 256 + 4 * 64) * sizeof(float);
    const size_t S2  = (size_t)(64 * PH + 256 * PL + 3 * 64 * PL + 16 * PL + 64 * 20 + 16 + 64) * sizeof(float);
    const size_t S3a = (size_t)(3 * 64 * PL) * sizeof(float);
    const size_t S3b = (size_t)(64 * PH + 2 * 64 * PL + 2 * 256 + 128) * sizeof(float);

    cudaFuncSetAttribute(k1,  cudaFuncAttributeMaxDynamicSharedMemorySize, (int)S1);
    cudaFuncSetAttribute(k2,  cudaFuncAttributeMaxDynamicSharedMemorySize, (int)S2);
    cudaFuncSetAttribute(k3a, cudaFuncAttributeMaxDynamicSharedMemorySize, (int)S3a);
    cudaFuncSetAttribute(k3b, cudaFuncAttributeMaxDynamicSharedMemorySize, (int)S3b);

    void* pM = nullptr; void* pwsum = nullptr;
    cudaGetSymbolAddress(&pM, g_M);
    cudaGetSymbolAddress(&pwsum, g_wsum);
    cudaMemsetAsync(pM, 0, (size_t)NB * SD * LD * sizeof(float), 0);
    cudaMemsetAsync(pwsum, 0, (size_t)NB * SD * sizeof(float), 0);

    k0<<<128, 256>>>(Wsh, Wasn, Win, Wout);
    k1<<<NB * BPB, 256, S1>>>(x, geo, ln1g, ln1b, bsh, basn);
    k2<<<NB, 256, S2>>>(Wfe, bfe, Wd, bd, gdn, bdn, Wanc, banc, Wself, Wctx, gon, bon, Wup, bup);
    k3a<<<NB * BPB, 256, S3a>>>(x, out);
    k3b<<<NB * BPB, 256, S3b>>>(ln2g, ln2b, binp, boutp, out);
}

// round 15
// speedup vs baseline: 1.1553x; 1.0339x over previous
#include <cuda_runtime.h>
#include <math.h>

#define NB   4
#define NTOK 65536
#define CD   256
#define LD   64
#define SD   64
#define TT   64
#define BPB  74
#define BPB3A 148
#define NTILE 1024
#define PH 260
#define PL 68

__device__ float g_w[(size_t)NB * NTOK * SD];   // softmax weights (tf32)
__device__ float g_M[NB * SD * LD];
__device__ float g_wsum[NB * SD];
__device__ float g_st[NB * SD * CD];            // st (tf32, row-major)
__device__ float g_WshT[CD * LD];               // tf32 Wsh
__device__ float g_WasnT[2 * LD * SD];          // tf32 Wasn (128x64)
__device__ float g_WinT[CD * 128];              // tf32 Win
__device__ float g_WoutT[LD * CD];              // tf32 Wout

__device__ __forceinline__ float geluf(float x) {
    return 0.5f * x * (1.0f + erff(x * 0.70710678118654752f));
}
__device__ __forceinline__ float sigm(float x) { return 1.0f / (1.0f + __expf(-x)); }

__device__ __forceinline__ float totf(float x) {
    unsigned r;
    asm("cvt.rna.tf32.f32 %0, %1;" : "=r"(r) : "f"(x));
    return __uint_as_float(r);
}

__device__ __forceinline__ void mma8(float (&d)[4], const unsigned (&a)[4], const unsigned (&b)[2]) {
    asm volatile("mma.sync.aligned.m16n8k8.row.col.f32.tf32.tf32.f32 "
                 "{%0,%1,%2,%3}, {%4,%5,%6,%7}, {%8,%9}, {%0,%1,%2,%3};"
                 : "+f"(d[0]), "+f"(d[1]), "+f"(d[2]), "+f"(d[3])
                 : "r"(a[0]), "r"(a[1]), "r"(a[2]), "r"(a[3]), "r"(b[0]), "r"(b[1]));
}

// warp mma: acc(16x32) += A(64 rows x 64 k, smem pitch lda) @ B(64x64 smem chunk, pitch PL)
__device__ __forceinline__ void mma_warp64(const float* __restrict__ sA, int lda,
                                           const float* __restrict__ sB,
                                           int wr, int wc, int g, int q, float (&acc)[4][4])
{
#pragma unroll
    for (int k8 = 0; k8 < 64; k8 += 8) {
        const float* Ab = sA + (wr * 16 + g) * lda + k8 + q;
        unsigned a[4] = { __float_as_uint(Ab[0]), __float_as_uint(Ab[8 * lda]),
                          __float_as_uint(Ab[4]), __float_as_uint(Ab[8 * lda + 4]) };
#pragma unroll
        for (int t = 0; t < 4; t++) {
            const float* Bb = sB + (k8 + q) * PL + wc * 32 + t * 8 + g;
            unsigned b[2] = { __float_as_uint(Bb[0]), __float_as_uint(Bb[4 * PL]) };
            mma8(acc[t], a, b);
        }
    }
}

// ---------- cp.async staging (16B granules) into pitch-PL smem ----------
__device__ __forceinline__ void cp_stage(float* dst, const float* __restrict__ src,
                                         int sld, int tid)
{
    for (int i = tid; i < 1024; i += 256) {
        int r = i >> 4, c4 = (i & 15) * 4;
        unsigned ds = (unsigned)__cvta_generic_to_shared(dst + r * PL + c4);
        asm volatile("cp.async.cg.shared.global [%0], [%1], 16;"
                     :: "r"(ds), "l"(src + r * sld + c4) : "memory");
    }
}
#define CP_COMMIT() asm volatile("cp.async.commit_group;" ::: "memory")
#define CP_WAIT(n)  asm volatile("cp.async.wait_group %0;" :: "n"(n) : "memory")

// ---------- scalar micro-kernel (k2 only) ----------
__device__ __forceinline__ void mm64(const float* __restrict__ A, int ald,
                                     const float* __restrict__ B, int bld,
                                     int tr, int tc, float (&acc)[4][4])
{
#pragma unroll 8
    for (int kk = 0; kk < 64; kk++) {
        float4 b4 = *reinterpret_cast<const float4*>(B + kk * bld + tc * 4);
        float a[4] = { A[tr * ald + kk], A[(tr + 16) * ald + kk],
                       A[(tr + 32) * ald + kk], A[(tr + 48) * ald + kk] };
        float bb[4] = { b4.x, b4.y, b4.z, b4.w };
#pragma unroll
        for (int i = 0; i < 4; i++)
#pragma unroll
            for (int j = 0; j < 4; j++) acc[i][j] = fmaf(a[i], bb[j], acc[i][j]);
    }
}

__device__ __forceinline__ void stage64c(float* dst, const float* __restrict__ src,
                                         int sld, int tid)
{
    for (int i = tid; i < 1024; i += 256) {
        int r = i >> 4, c4 = (i & 15) * 4;
        *reinterpret_cast<float4*>(dst + r * PL + c4) =
            *reinterpret_cast<const float4*>(src + r * sld + c4);
    }
}

__device__ __forceinline__ void ln64(const float* src, float* dst,
                                     const float* __restrict__ gg, const float* __restrict__ bb,
                                     int warp, int lane)
{
#pragma unroll 1
    for (int q = 0; q < 8; q++) {
        int s = warp * 8 + q;
        float v0 = src[s * PL + lane], v1 = src[s * PL + lane + 32];
        float s1 = v0 + v1, s2 = v0 * v0 + v1 * v1;
#pragma unroll
        for (int o = 16; o > 0; o >>= 1) {
            s1 += __shfl_xor_sync(~0u, s1, o);
            s2 += __shfl_xor_sync(~0u, s2, o);
        }
        float m = s1 * (1.0f / 64.0f);
        float r = rsqrtf(fmaxf(s2 * (1.0f / 64.0f) - m * m, 0.0f) + 1e-5f);
        dst[s * PL + lane]      = (v0 - m) * r * gg[lane] + bb[lane];
        dst[s * PL + lane + 32] = (v1 - m) * r * gg[lane + 32] + bb[lane + 32];
    }
}

// ============================ K0: tf32-round all mma B weights ============================
extern "C" __global__ void k0(const float* __restrict__ Wsh, const float* __restrict__ Wasn,
                              const float* __restrict__ Win, const float* __restrict__ Wout)
{
    int i = blockIdx.x * 256 + threadIdx.x;
    if (i < CD * LD)     g_WshT[i] = totf(Wsh[i]);
    if (i < 2 * LD * SD) g_WasnT[i] = totf(Wasn[i]);
    if (i < CD * 128)    g_WinT[i] = totf(Win[i]);
    if (i < LD * CD)     g_WoutT[i] = totf(Wout[i]);
}

// ============================ K1: phase 1 (all-mma, cp.async pipelined) ============================
extern "C" __global__ void __launch_bounds__(256, 2)
k1(const float* __restrict__ xg, const float* __restrict__ geo,
   const float* __restrict__ g1, const float* __restrict__ b1,
   const float* __restrict__ bsh, const float* __restrict__ basn)
{
    extern __shared__ float sm[];
    float* sX   = sm;                 // 64 x PL  (normalized x chunk; later w^T)
    float* sSh  = sX + 64 * PL;       // 64 x PL  (shared, tf32)
    float* sLg  = sSh + 64 * PL;      // 64 x PL  (logits -> w fp32)
    float* sGeo = sLg + 64 * PL;      // 64 x PL  (geo, tf32)
    float* wb0  = sGeo + 64 * PL;     // stage buffer 0
    float* wb1  = wb0 + 64 * PL;      // stage buffer 1
    float* sG1  = wb1 + 64 * PL;      // 256
    float* sB1  = sG1 + 256;          // 256
    float* sMean = sB1 + 256;         // 64
    float* sRstd = sMean + 64;        // 64
    float* sBsh = sRstd + 64;         // 64
    float* sBa  = sBsh + 64;          // 64

    const int tid = threadIdx.x;
    const int warp = tid >> 5, lane = tid & 31;
    const int wr = warp >> 1, wc = warp & 1;
    const int g = lane >> 2, q = lane & 3;
    const int b = blockIdx.x / BPB, rb = blockIdx.x % BPB;
    float* wb[2] = { wb0, wb1 };

    sG1[tid] = g1[tid]; sB1[tid] = b1[tid];
    if (tid < 64) { sBsh[tid] = bsh[tid]; sBa[tid] = basn[tid]; }
    float wloc = 0.0f;
    float Macc[4][4] = {};   // persistent w^T @ shared accumulator (mma fragments)
    __syncthreads();

    for (int tile = rb; tile < NTILE; tile += BPB) {
        const size_t tok0 = (size_t)b * NTOK + (size_t)tile * TT;
        __syncthreads();   // prev tile readers of all smem done

        cp_stage(wb0, g_WshT, 64, tid);
        CP_COMMIT();

        // LN stats
#pragma unroll 1
        for (int qq = 0; qq < 8; qq++) {
            int t = warp * 8 + qq;
            const float* row = xg + (tok0 + t) * CD;
            float s1 = 0.0f, s2 = 0.0f;
#pragma unroll
            for (int k = 0; k < 8; k++) { float v = row[lane + 32 * k]; s1 += v; s2 += v * v; }
#pragma unroll
            for (int o = 16; o > 0; o >>= 1) {
                s1 += __shfl_xor_sync(~0u, s1, o);
                s2 += __shfl_xor_sync(~0u, s2, o);
            }
            if (lane == 0) {
                float m = s1 * (1.0f / 256.0f);
                sMean[t] = m;
                sRstd[t] = rsqrtf(fmaxf(s2 * (1.0f / 256.0f) - m * m, 0.0f) + 1e-5f);
            }
        }
        // geo -> sGeo (tf32)
        for (int i = tid; i < 1024; i += 256) {
            int t = i >> 4, c4 = (i & 15) * 4;
            float4 v = *reinterpret_cast<const float4*>(geo + (tok0 + t) * LD + c4);
            *reinterpret_cast<float4*>(sGeo + t * PL + c4) =
                make_float4(totf(v.x), totf(v.y), totf(v.z), totf(v.w));
        }
        __syncthreads();   // stats visible

        // GEMM1 (pipelined): shared = LN(x) @ Wsh
        float a1[4][4] = {};
#pragma unroll 1
        for (int kt = 0; kt < 4; kt++) {
            const int base = kt * 64;
#pragma unroll
            for (int ii = 0; ii < 4; ii++) {
                int idx = tid + ii * 256;
                int r = idx >> 4, c4 = (idx & 15) * 4;
                float4 xv = *reinterpret_cast<const float4*>(xg + (tok0 + r) * CD + base + c4);
                float m = sMean[r], rs = sRstd[r];
                *reinterpret_cast<float4*>(sX + r * PL + c4) = make_float4(
                    totf((xv.x - m) * rs * sG1[base + c4 + 0] + sB1[base + c4 + 0]),
                    totf((xv.y - m) * rs * sG1[base + c4 + 1] + sB1[base + c4 + 1]),
                    totf((xv.z - m) * rs * sG1[base + c4 + 2] + sB1[base + c4 + 2]),
                    totf((xv.w - m) * rs * sG1[base + c4 + 3] + sB1[base + c4 + 3]));
            }
            if (kt < 3) { cp_stage(wb[(kt + 1) & 1], g_WshT + (kt + 1) * 64 * 64, 64, tid); CP_COMMIT(); }
            if (kt < 3) { CP_WAIT(1); } else { CP_WAIT(0); }
            __syncthreads();
            mma_warp64(sX, PL, wb[kt & 1], wr, wc, g, q, a1);
            __syncthreads();
        }
        // shared -> sSh (tf32 + bias); prefetch both Wasn chunks
#pragma unroll
        for (int t = 0; t < 4; t++) {
            int col = wc * 32 + t * 8 + 2 * q;
            int r0 = (wr * 16 + g) * PL, r1 = r0 + 8 * PL;
            sSh[r0 + col]     = totf(a1[t][0] + sBsh[col]);
            sSh[r0 + col + 1] = totf(a1[t][1] + sBsh[col + 1]);
            sSh[r1 + col]     = totf(a1[t][2] + sBsh[col]);
            sSh[r1 + col + 1] = totf(a1[t][3] + sBsh[col + 1]);
        }
        cp_stage(wb0, g_WasnT, 64, tid);
        cp_stage(wb1, g_WasnT + 64 * 64, 64, tid);
        CP_COMMIT();
        CP_WAIT(0);
        __syncthreads();   // sSh + Wasn visible; sX reads done (w^T store safe)

        // GEMM3: logits = shared@Wasn0 + geo@Wasn1
        float a3[4][4] = {};
        mma_warp64(sSh, PL, wb0, wr, wc, g, q, a3);
        mma_warp64(sGeo, PL, wb1, wr, wc, g, q, a3);
#pragma unroll
        for (int t = 0; t < 4; t++) {
            int col = wc * 32 + t * 8 + 2 * q;
            int r0 = (wr * 16 + g) * PL, r1 = r0 + 8 * PL;
            sLg[r0 + col]     = a3[t][0] + sBa[col];
            sLg[r0 + col + 1] = a3[t][1] + sBa[col + 1];
            sLg[r1 + col]     = a3[t][2] + sBa[col];
            sLg[r1 + col + 1] = a3[t][3] + sBa[col + 1];
        }
        __syncthreads();

        // softmax -> w : fp32 in sLg, tf32 spill to g_w, tf32 transpose into sX (w^T)
#pragma unroll 1
        for (int qq = 0; qq < 8; qq++) {
            int t = warp * 8 + qq;
            float v0 = sLg[t * PL + lane], v1 = sLg[t * PL + lane + 32];
            float mx = fmaxf(v0, v1);
#pragma unroll
            for (int o = 16; o > 0; o >>= 1) mx = fmaxf(mx, __shfl_xor_sync(~0u, mx, o));
            float e0 = __expf(v0 - mx), e1 = __expf(v1 - mx), ss = e0 + e1;
#pragma unroll
            for (int o = 16; o > 0; o >>= 1) ss += __shfl_xor_sync(~0u, ss, o);
            float inv = 1.0f / ss;
            float w0 = e0 * inv, w1 = e1 * inv;
            float t0 = totf(w0), t1 = totf(w1);
            sLg[t * PL + lane] = w0; sLg[t * PL + lane + 32] = w1;
            sX[lane * PL + t] = t0; sX[(lane + 32) * PL + t] = t1;   // w^T
            float* wo = g_w + (tok0 + t) * SD;
            wo[lane] = t0; wo[lane + 32] = t1;
        }
        __syncthreads();

        if (tid < 64) {
            float cs = 0.0f;
            for (int t = 0; t < 64; t++) cs += sLg[t * PL + tid];
            wloc += cs;
        }
        // GEMM4': Macc += w^T @ shared  (tf32 mma, persistent fragment accumulators)
        mma_warp64(sX, PL, sSh, wr, wc, g, q, Macc);
    }

    if (tid < 64) atomicAdd(&g_wsum[b * 64 + tid], wloc);
#pragma unroll
    for (int t = 0; t < 4; t++) {
        int col = wc * 32 + t * 8 + 2 * q;
        int r0 = wr * 16 + g, r1 = r0 + 8;
        atomicAdd(&g_M[b * 4096 + r0 * 64 + col],     Macc[t][0]);
        atomicAdd(&g_M[b * 4096 + r0 * 64 + col + 1], Macc[t][1]);
        atomicAdd(&g_M[b * 4096 + r1 * 64 + col],     Macc[t][2]);
        atomicAdd(&g_M[b * 4096 + r1 * 64 + col + 1], Macc[t][3]);
    }
}

// ============================ K2: slice reconstruction + latent transition ============================
extern "C" __global__ void __launch_bounds__(256, 1)
k2(const float* __restrict__ Wfe, const float* __restrict__ bfe,
   const float* __restrict__ Wd, const float* __restrict__ bd,
   const float* __restrict__ gdn, const float* __restrict__ bdn,
   const float* __restrict__ Wanc, const float* __restrict__ banc,
   const float* __restrict__ Wself, const float* __restrict__ Wctx,
   const float* __restrict__ gon, const float* __restrict__ bon,
   const float* __restrict__ Wup, const float* __restrict__ bup)
{
    extern __shared__ float sm[];
    float* sS  = sm;               // 64 x PH
    float* sWb = sS + 64 * PH;     // 256 x PL
    float* sT1 = sWb + 256 * PL;   // 64 x PL
    float* sT2 = sT1 + 64 * PL;    // 64 x PL
    float* sCx = sT2 + 64 * PL;    // 64 x PL
    float* sAn = sCx + 64 * PL;    // 16 x PL
    float* sAw = sAn + 16 * PL;    // 64 x 20
    float* sAs = sAw + 64 * 20;    // 16
    float* sWm = sAs + 16;         // 64

    const int tid = threadIdx.x;
    const int tr = tid >> 4, tc = tid & 15;
    const int warp = tid >> 5, lane = tid & 31;
    const int b = blockIdx.x;

    if (tid < 64) sWm[tid] = fmaxf(g_wsum[b * 64 + tid], 1e-6f);
    for (int i = tid; i < 64 * 64; i += 256) {
        int s = i >> 6, l = i & 63;
        sT1[s * PL + l] = g_M[b * 4096 + i];
    }
    __syncthreads();

    for (int cc = 0; cc < 4; cc++) {
        __syncthreads();
        stage64c(sWb, Wfe + cc * 64, 256, tid);
        __syncthreads();
        float acc[4][4] = {};
        mm64(sT1, PL, sWb, PL, tr, tc, acc);
#pragma unroll
        for (int i = 0; i < 4; i++)
#pragma unroll
            for (int j = 0; j < 4; j++) {
                int s = tr + 16 * i, c = cc * 64 + tc * 4 + j;
                float ws = sWm[s];
                sS[s * PH + c] = (acc[i][j] + ws * bfe[c]) / ws;
            }
    }
    __syncthreads();

    for (int i = tid; i < 256 * 16; i += 256) {
        int r = i >> 4, c4 = (i & 15) * 4;
        *reinterpret_cast<float4*>(sWb + r * PL + c4) =
            *reinterpret_cast<const float4*>(Wd + r * 64 + c4);
    }
    __syncthreads();
    {
        float acc[4][4] = {};
        for (int kt = 0; kt < 4; kt++)
            mm64(sS + kt * 64, PH, sWb + kt * 64 * PL, PL, tr, tc, acc);
        __syncthreads();
#pragma unroll
        for (int i = 0; i < 4; i++)
#pragma unroll
            for (int j = 0; j < 4; j++) {
                int c = tc * 4 + j;
                sT2[(tr + 16 * i) * PL + c] = acc[i][j] + bd[c];
            }
    }
    __syncthreads();
    ln64(sT2, sT1, gdn, bdn, warp, lane);
    __syncthreads();

    {
        int s = tid >> 2, a0 = (tid & 3) * 4;
        float a4[4] = {0.f, 0.f, 0.f, 0.f};
        for (int k = 0; k < 64; k++) {
            float av = sT1[s * PL + k];
#pragma unroll
            for (int j = 0; j < 4; j++) a4[j] = fmaf(av, Wanc[k * 16 + a0 + j], a4[j]);
        }
#pragma unroll
        for (int j = 0; j < 4; j++) sAw[s * 20 + a0 + j] = a4[j] + banc[a0 + j];
    }
    __syncthreads();
    if (tid < 64) {
        float mx = -1e30f;
        for (int a = 0; a < 16; a++) mx = fmaxf(mx, sAw[tid * 20 + a]);
        float e[16], ss = 0.0f;
        for (int a = 0; a < 16; a++) { e[a] = __expf(sAw[tid * 20 + a] - mx); ss += e[a]; }
        float inv = 1.0f / ss;
        for (int a = 0; a < 16; a++) sAw[tid * 20 + a] = e[a] * inv;
    }
    __syncthreads();
    if (tid < 16) {
        float cs = 0.0f;
        for (int s = 0; s < 64; s++) cs += sAw[s * 20 + tid];
        sAs[tid] = fmaxf(cs, 1e-6f);
    }
    __syncthreads();
    for (int idx = tid; idx < 16 * 64; idx += 256) {
        int a = idx >> 6, d = idx & 63;
        float s = 0.0f;
        for (int t = 0; t < 64; t++) s = fmaf(sAw[t * 20 + a], sT1[t * PL + d], s);
        sAn[a * PL + d] = s / sAs[a];
    }
    __syncthreads();
    for (int idx = tid; idx < 64 * 64; idx += 256) {
        int s = idx >> 6, d = idx & 63;
        float v = 0.0f;
#pragma unroll
        for (int a = 0; a < 16; a++) v = fmaf(sAw[s * 20 + a], sAn[a * PL + d], v);
        sCx[s * PL + d] = v;
    }
    __syncthreads();

    {
        float acc[4][4] = {};
        for (int i = tid; i < 64 * 16; i += 256) {
            int r = i >> 4, c4 = (i & 15) * 4;
            *reinterpret_cast<float4*>(sWb + r * PL + c4) =
                *reinterpret_cast<const float4*>(Wself + r * 64 + c4);
        }
        __syncthreads();
        mm64(sT1, PL, sWb, PL, tr, tc, acc);
        __syncthreads();
        for (int i = tid; i < 64 * 16; i += 256) {
            int r = i >> 4, c4 = (i & 15) * 4;
            *reinterpret_cast<float4*>(sWb + r * PL + c4) =
                *reinterpret_cast<const float4*>(Wctx + r * 64 + c4);
        }
        __syncthreads();
        mm64(sCx, PL, sWb, PL, tr, tc, acc);
#pragma unroll
        for (int i = 0; i < 4; i++)
#pragma unroll
            for (int j = 0; j < 4; j++) {
                int row = tr + 16 * i, c = tc * 4 + j;
                sT2[row * PL + c] = sT1[row * PL + c] + geluf(acc[i][j]);
            }
    }
    __syncthreads();
    ln64(sT2, sCx, gon, bon, warp, lane);
    __syncthreads();

    // st = LN(ul)@Wup + bup (tf32, row-major)
    for (int cc = 0; cc < 4; cc++) {
        __syncthreads();
        for (int i = tid; i < 64 * 16; i += 256) {
            int r = i >> 4, c4 = (i & 15) * 4;
            *reinterpret_cast<float4*>(sWb + r * PL + c4) =
                *reinterpret_cast<const float4*>(Wup + r * 256 + cc * 64 + c4);
        }
        __syncthreads();
        float acc[4][4] = {};
        mm64(sCx, PL, sWb, PL, tr, tc, acc);
#pragma unroll
        for (int i = 0; i < 4; i++)
#pragma unroll
            for (int j = 0; j < 4; j++) {
                int row = tr + 16 * i, c = cc * 64 + tc * 4 + j;
                g_st[b * 16384 + row * 256 + c] = totf(acc[i][j] + bup[c]);
            }
    }
}

// ============================ K3a: y = x + w@st (pipelined, 4 CTAs/SM) ============================
extern "C" __global__ void __launch_bounds__(256, 4)
k3a(const float* __restrict__ xg, float* __restrict__ out)
{
    extern __shared__ float sm[];
    float* sWt = sm;               // 64 x PL : w tile (A)
    float* sb0 = sWt + 64 * PL;    // stage buffers
    float* sb1 = sb0 + 64 * PL;

    const int tid = threadIdx.x;
    const int warp = tid >> 5, lane = tid & 31;
    const int wr = warp >> 1, wc = warp & 1;
    const int g = lane >> 2, q = lane & 3;
    const int b = blockIdx.x / BPB3A, rb = blockIdx.x % BPB3A;
    float* sb[2] = { sb0, sb1 };

    for (int tile = rb; tile < NTILE; tile += BPB3A) {
        const size_t tok0 = (size_t)b * NTOK + (size_t)tile * TT;
        __syncthreads();   // prev tile readers done

        cp_stage(sWt, g_w + tok0 * SD, SD, tid);
        cp_stage(sb0, g_st + b * 16384, 256, tid);
        CP_COMMIT();

#pragma unroll 1
        for (int cc = 0; cc < 4; cc++) {
            if (cc < 3) { cp_stage(sb[(cc + 1) & 1], g_st + b * 16384 + (cc + 1) * 64, 256, tid); CP_COMMIT(); }
            if (cc < 3) { CP_WAIT(1); } else { CP_WAIT(0); }
            __syncthreads();
            float acc[4][4] = {};
            mma_warp64(sWt, PL, sb[cc & 1], wr, wc, g, q, acc);
#pragma unroll
            for (int t = 0; t < 4; t++) {
                int col = cc * 64 + wc * 32 + t * 8 + 2 * q;
                size_t r0 = (tok0 + wr * 16 + g) * CD + col;
                size_t r1 = r0 + 8 * CD;
                float2 x0 = *reinterpret_cast<const float2*>(xg + r0);
                float2 x1 = *reinterpret_cast<const float2*>(xg + r1);
                *reinterpret_cast<float2*>(out + r0) = make_float2(acc[t][0] + x0.x, acc[t][1] + x0.y);
                *reinterpret_cast<float2*>(out + r1) = make_float2(acc[t][2] + x1.x, acc[t][3] + x1.y);
            }
            __syncthreads();
        }
    }
}

// ============================ K3b: LN2 + GLU + out-proj (pipelined) ============================
extern "C" __global__ void __launch_bounds__(256, 2)
k3b(const float* __restrict__ g2, const float* __restrict__ b2,
    const float* __restrict__ binp, const float* __restrict__ boutp,
    float* __restrict__ out)
{
    extern __shared__ float sm[];
    float* sH  = sm;               // 64 x PH : LN2(y) tf32; first 64xPL reused for act
    float* bb0 = sH + 64 * PH;     // stage buffers
    float* bb1 = bb0 + 64 * PL;
    float* sG2 = bb1 + 64 * PL;    // 256
    float* sB2 = sG2 + 256;        // 256
    float* sBi = sB2 + 256;        // 128

    const int tid = threadIdx.x;
    const int warp = tid >> 5, lane = tid & 31;
    const int wr = warp >> 1, wc = warp & 1;
    const int g = lane >> 2, q = lane & 3;
    const int b = blockIdx.x / BPB, rb = blockIdx.x % BPB;
    float* bb[2] = { bb0, bb1 };
    float* sAct = sH;              // alias, pitch PL

    sG2[tid] = g2[tid]; sB2[tid] = b2[tid];
    if (tid < 128) sBi[tid] = binp[tid];
    __syncthreads();

    for (int tile = rb; tile < NTILE; tile += BPB) {
        const size_t tok0 = (size_t)b * NTOK + (size_t)tile * TT;
        __syncthreads();   // prev tile readers done

        cp_stage(bb0, g_WinT, 128, tid);   // Win chunk (kt=0, v-half)
        CP_COMMIT();

        // LN2: y (from out, written by k3a) -> h (tf32) in sH
#pragma unroll 1
        for (int qq = 0; qq < 8; qq++) {
            int t = warp * 8 + qq;
            const float* yrow = out + (tok0 + t) * CD;
            float v[8], s1 = 0.0f, s2 = 0.0f;
#pragma unroll
            for (int k = 0; k < 8; k++) { v[k] = yrow[lane + 32 * k]; s1 += v[k]; s2 += v[k] * v[k]; }
#pragma unroll
            for (int o = 16; o > 0; o >>= 1) {
                s1 += __shfl_xor_sync(~0u, s1, o);
                s2 += __shfl_xor_sync(~0u, s2, o);
            }
            float m = s1 * (1.0f / 256.0f);
            float r = rsqrtf(fmaxf(s2 * (1.0f / 256.0f) - m * m, 0.0f) + 1e-5f);
#pragma unroll
            for (int k = 0; k < 8; k++) {
                int c = lane + 32 * k;
                sH[t * PH + c] = totf((v[k] - m) * r * sG2[c] + sB2[c]);
            }
        }
        __syncthreads();   // sH visible

        // GEMM B: vg = h @ Win   (8 chunks: c = kt*2 + h)
        float accv[4][4] = {}, accg[4][4] = {};
#pragma unroll 1
        for (int c = 0; c < 8; c++) {
            if (c < 7) {
                int nkt = (c + 1) >> 1, nh = (c + 1) & 1;
                cp_stage(bb[(c + 1) & 1], g_WinT + nkt * 64 * 128 + nh * 64, 128, tid);
                CP_COMMIT();
            }
            if (c < 7) { CP_WAIT(1); } else { CP_WAIT(0); }
            __syncthreads();
            if (c & 1) mma_warp64(sH + (c >> 1) * 64, PH, bb[c & 1], wr, wc, g, q, accg);
            else       mma_warp64(sH + (c >> 1) * 64, PH, bb[c & 1], wr, wc, g, q, accv);
            __syncthreads();
        }

        cp_stage(bb0, g_WoutT, 256, tid);
        CP_COMMIT();

        // act -> sAct (reuses sH start; GEMM B reads done)
#pragma unroll
        for (int t = 0; t < 4; t++) {
            int col = wc * 32 + t * 8 + 2 * q;
            int s0 = (wr * 16 + g) * PL + col;
            int s1 = s0 + 8 * PL;
            sAct[s0]     = totf(geluf(accv[t][0] + sBi[col])     * sigm(accg[t][0] + sBi[64 + col]));
            sAct[s0 + 1] = totf(geluf(accv[t][1] + sBi[col + 1]) * sigm(accg[t][1] + sBi[64 + col + 1]));
            sAct[s1]     = totf(geluf(accv[t][2] + sBi[col])     * sigm(accg[t][2] + sBi[64 + col]));
            sAct[s1 + 1] = totf(geluf(accv[t][3] + sBi[col + 1]) * sigm(accg[t][3] + sBi[64 + col + 1]));
        }

        // GEMM C: out = y + act @ Wout + bout
#pragma unroll 1
        for (int cc = 0; cc < 4; cc++) {
            if (cc < 3) { cp_stage(bb[(cc + 1) & 1], g_WoutT + (cc + 1) * 64, 256, tid); CP_COMMIT(); }
            if (cc < 3) { CP_WAIT(1); } else { CP_WAIT(0); }
            __syncthreads();   // act (cc=0) + staged chunk visible
            float acc[4][4] = {};
            mma_warp64(sAct, PL, bb[cc & 1], wr, wc, g, q, acc);
#pragma unroll
            for (int t = 0; t < 4; t++) {
                int col = cc * 64 + wc * 32 + t * 8 + 2 * q;
                size_t r0 = (tok0 + wr * 16 + g) * CD + col;
                size_t r1 = r0 + 8 * CD;
                float2 y0 = *reinterpret_cast<const float2*>(out + r0);
                float2 y1 = *reinterpret_cast<const float2*>(out + r1);
                float2 bo = *reinterpret_cast<const float2*>(boutp + col);
                *reinterpret_cast<float2*>(out + r0) =
                    make_float2(y0.x + acc[t][0] + bo.x, y0.y + acc[t][1] + bo.y);
                *reinterpret_cast<float2*>(out + r1) =
                    make_float2(y1.x + acc[t][2] + bo.x, y1.y + acc[t][3] + bo.y);
            }
            __syncthreads();
        }
    }
}

// ============================ launcher ============================
extern "C" void kernel_launch(void* const* d_in, const int* in_sizes, int n_in,
                              void* d_out, int out_size)
{
    const float* x     = (const float*)d_in[0];
    const float* geo   = (const float*)d_in[1];
    const float* ln1g  = (const float*)d_in[2];
    const float* ln1b  = (const float*)d_in[3];
    const float* Wsh   = (const float*)d_in[4];
    const float* bsh   = (const float*)d_in[5];
    const float* Wfe   = (const float*)d_in[6];
    const float* bfe   = (const float*)d_in[7];
    const float* Wasn  = (const float*)d_in[8];
    const float* basn  = (const float*)d_in[9];
    const float* Wd    = (const float*)d_in[10];
    const float* bd    = (const float*)d_in[11];
    const float* gdn   = (const float*)d_in[12];
    const float* bdn   = (const float*)d_in[13];
    const float* Wanc  = (const float*)d_in[14];
    const float* banc  = (const float*)d_in[15];
    const float* Wself = (const float*)d_in[16];
    const float* Wctx  = (const float*)d_in[17];
    const float* gon   = (const float*)d_in[18];
    const float* bon   = (const float*)d_in[19];
    const float* Wup   = (const float*)d_in[20];
    const float* bup   = (const float*)d_in[21];
    const float* ln2g  = (const float*)d_in[22];
    const float* ln2b  = (const float*)d_in[23];
    const float* Win   = (const float*)d_in[24];
    const float* binp  = (const float*)d_in[25];
    const float* Wout  = (const float*)d_in[26];
    const float* boutp = (const float*)d_in[27];
    float* out = (float*)d_out;

    const size_t S1  = (size_t)(6 * 64 * PL + 2 * 256 + 4 * 64) * sizeof(float);
    const size_t S2  = (size_t)(64 * PH + 256 * PL + 3 * 64 * PL + 16 * PL + 64 * 20 + 16 + 64) * sizeof(float);
    const size_t S3a = (size_t)(3 * 64 * PL) * sizeof(float);
    const size_t S3b = (size_t)(64 * PH + 2 * 64 * PL + 2 * 256 + 128) * sizeof(float);

    cudaFuncSetAttribute(k1,  cudaFuncAttributeMaxDynamicSharedMemorySize, (int)S1);
    cudaFuncSetAttribute(k2,  cudaFuncAttributeMaxDynamicSharedMemorySize, (int)S2);
    cudaFuncSetAttribute(k3a, cudaFuncAttributeMaxDynamicSharedMemorySize, (int)S3a);
    cudaFuncSetAttribute(k3b, cudaFuncAttributeMaxDynamicSharedMemorySize, (int)S3b);

    void* pM = nullptr; void* pwsum = nullptr;
    cudaGetSymbolAddress(&pM, g_M);
    cudaGetSymbolAddress(&pwsum, g_wsum);
    cudaMemsetAsync(pM, 0, (size_t)NB * SD * LD * sizeof(float), 0);
    cudaMemsetAsync(pwsum, 0, (size_t)NB * SD * sizeof(float), 0);

    k0<<<128, 256>>>(Wsh, Wasn, Win, Wout);
    k1<<<NB * BPB, 256, S1>>>(x, geo, ln1g, ln1b, bsh, basn);
    k2<<<NB, 256, S2>>>(Wfe, bfe, Wd, bd, gdn, bdn, Wanc, banc, Wself, Wctx, gon, bon, Wup, bup);
    k3a<<<NB * BPB3A, 256, S3a>>>(x, out);
    k3b<<<NB * BPB, 256, S3b>>>(ln2g, ln2b, binp, boutp, out);
}

// round 17
// speedup vs baseline: 1.2208x; 1.0566x over previous
#include <cuda_runtime.h>
#include <math.h>

#define NB   4
#define NTOK 65536
#define CD   256
#define LD   64
#define SD   64
#define TT   64
#define BPB  74
#define NTILE 1024
#define PH 260
#define PL 68

__device__ float g_w[(size_t)NB * NTOK * SD];   // softmax weights (tf32)
__device__ float g_M[NB * SD * LD];
__device__ float g_wsum[NB * SD];
__device__ float g_st[NB * SD * CD];            // st (tf32, row-major)
__device__ float g_WshT[CD * LD];               // tf32 Wsh
__device__ float g_WasnT[2 * LD * SD];          // tf32 Wasn (128x64)
__device__ float g_WinT[CD * 128];              // tf32 Win
__device__ float g_WoutT[LD * CD];              // tf32 Wout

__device__ __forceinline__ float geluf(float x) {
    return 0.5f * x * (1.0f + erff(x * 0.70710678118654752f));
}
__device__ __forceinline__ float sigm(float x) { return 1.0f / (1.0f + __expf(-x)); }

__device__ __forceinline__ float totf(float x) {
    unsigned r;
    asm("cvt.rna.tf32.f32 %0, %1;" : "=r"(r) : "f"(x));
    return __uint_as_float(r);
}

__device__ __forceinline__ void mma8(float (&d)[4], const unsigned (&a)[4], const unsigned (&b)[2]) {
    asm volatile("mma.sync.aligned.m16n8k8.row.col.f32.tf32.tf32.f32 "
                 "{%0,%1,%2,%3}, {%4,%5,%6,%7}, {%8,%9}, {%0,%1,%2,%3};"
                 : "+f"(d[0]), "+f"(d[1]), "+f"(d[2]), "+f"(d[3])
                 : "r"(a[0]), "r"(a[1]), "r"(a[2]), "r"(a[3]), "r"(b[0]), "r"(b[1]));
}

// warp mma: acc(16x32) += A(64 rows x 64 k, smem pitch lda) @ B(64x64 smem chunk, pitch PL)
__device__ __forceinline__ void mma_warp64(const float* __restrict__ sA, int lda,
                                           const float* __restrict__ sB,
                                           int wr, int wc, int g, int q, float (&acc)[4][4])
{
#pragma unroll
    for (int k8 = 0; k8 < 64; k8 += 8) {
        const float* Ab = sA + (wr * 16 + g) * lda + k8 + q;
        unsigned a[4] = { __float_as_uint(Ab[0]), __float_as_uint(Ab[8 * lda]),
                          __float_as_uint(Ab[4]), __float_as_uint(Ab[8 * lda + 4]) };
#pragma unroll
        for (int t = 0; t < 4; t++) {
            const float* Bb = sB + (k8 + q) * PL + wc * 32 + t * 8 + g;
            unsigned b[2] = { __float_as_uint(Bb[0]), __float_as_uint(Bb[4 * PL]) };
            mma8(acc[t], a, b);
        }
    }
}

// preload A fragments for a 64-k chunk (32 regs)
__device__ __forceinline__ void load_afrag(const float* __restrict__ sA, int lda,
                                           int wr, int g, int q, unsigned (&afr)[8][4])
{
#pragma unroll
    for (int k8 = 0; k8 < 8; k8++) {
        const float* Ab = sA + (wr * 16 + g) * lda + k8 * 8 + q;
        afr[k8][0] = __float_as_uint(Ab[0]);
        afr[k8][1] = __float_as_uint(Ab[8 * lda]);
        afr[k8][2] = __float_as_uint(Ab[4]);
        afr[k8][3] = __float_as_uint(Ab[8 * lda + 4]);
    }
}

// mma with preloaded A fragments
__device__ __forceinline__ void mma_pre(const unsigned (&afr)[8][4],
                                        const float* __restrict__ sB,
                                        int wc, int g, int q, float (&acc)[4][4])
{
#pragma unroll
    for (int k8 = 0; k8 < 8; k8++) {
#pragma unroll
        for (int t = 0; t < 4; t++) {
            const float* Bb = sB + (k8 * 8 + q) * PL + wc * 32 + t * 8 + g;
            unsigned b[2] = { __float_as_uint(Bb[0]), __float_as_uint(Bb[4 * PL]) };
            mma8(acc[t], afr[k8], b);
        }
    }
}

// ---------- cp.async staging (16B granules) into pitch-PL smem ----------
__device__ __forceinline__ void cp_stage(float* dst, const float* __restrict__ src,
                                         int sld, int tid)
{
    for (int i = tid; i < 1024; i += 256) {
        int r = i >> 4, c4 = (i & 15) * 4;
        unsigned ds = (unsigned)__cvta_generic_to_shared(dst + r * PL + c4);
        asm volatile("cp.async.cg.shared.global [%0], [%1], 16;"
                     :: "r"(ds), "l"(src + r * sld + c4) : "memory");
    }
}
#define CP_COMMIT() asm volatile("cp.async.commit_group;" ::: "memory")
#define CP_WAIT(n)  asm volatile("cp.async.wait_group %0;" :: "n"(n) : "memory")

// ---------- scalar micro-kernel (k2 only) ----------
__device__ __forceinline__ void mm64(const float* __restrict__ A, int ald,
                                     const float* __restrict__ B, int bld,
                                     int tr, int tc, float (&acc)[4][4])
{
#pragma unroll 8
    for (int kk = 0; kk < 64; kk++) {
        float4 b4 = *reinterpret_cast<const float4*>(B + kk * bld + tc * 4);
        float a[4] = { A[tr * ald + kk], A[(tr + 16) * ald + kk],
                       A[(tr + 32) * ald + kk], A[(tr + 48) * ald + kk] };
        float bb[4] = { b4.x, b4.y, b4.z, b4.w };
#pragma unroll
        for (int i = 0; i < 4; i++)
#pragma unroll
            for (int j = 0; j < 4; j++) acc[i][j] = fmaf(a[i], bb[j], acc[i][j]);
    }
}

__device__ __forceinline__ void stage64c(float* dst, const float* __restrict__ src,
                                         int sld, int tid)
{
    for (int i = tid; i < 1024; i += 256) {
        int r = i >> 4, c4 = (i & 15) * 4;
        *reinterpret_cast<float4*>(dst + r * PL + c4) =
            *reinterpret_cast<const float4*>(src + r * sld + c4);
    }
}

__device__ __forceinline__ void ln64(const float* src, float* dst,
                                     const float* __restrict__ gg, const float* __restrict__ bb,
                                     int warp, int lane)
{
#pragma unroll 1
    for (int q = 0; q < 8; q++) {
        int s = warp * 8 + q;
        float v0 = src[s * PL + lane], v1 = src[s * PL + lane + 32];
        float s1 = v0 + v1, s2 = v0 * v0 + v1 * v1;
#pragma unroll
        for (int o = 16; o > 0; o >>= 1) {
            s1 += __shfl_xor_sync(~0u, s1, o);
            s2 += __shfl_xor_sync(~0u, s2, o);
        }
        float m = s1 * (1.0f / 64.0f);
        float r = rsqrtf(fmaxf(s2 * (1.0f / 64.0f) - m * m, 0.0f) + 1e-5f);
        dst[s * PL + lane]      = (v0 - m) * r * gg[lane] + bb[lane];
        dst[s * PL + lane + 32] = (v1 - m) * r * gg[lane + 32] + bb[lane + 32];
    }
}

// ============================ K0: tf32-round all mma B weights ============================
extern "C" __global__ void k0(const float* __restrict__ Wsh, const float* __restrict__ Wasn,
                              const float* __restrict__ Win, const float* __restrict__ Wout)
{
    int i = blockIdx.x * 256 + threadIdx.x;
    if (i < CD * LD)     g_WshT[i] = totf(Wsh[i]);
    if (i < 2 * LD * SD) g_WasnT[i] = totf(Wasn[i]);
    if (i < CD * 128)    g_WinT[i] = totf(Win[i]);
    if (i < LD * CD)     g_WoutT[i] = totf(Wout[i]);
}

// ============================ K1: phase 1 (all-mma, cp.async pipelined) ============================
extern "C" __global__ void __launch_bounds__(256, 2)
k1(const float* __restrict__ xg, const float* __restrict__ geo,
   const float* __restrict__ g1, const float* __restrict__ b1,
   const float* __restrict__ bsh, const float* __restrict__ basn)
{
    extern __shared__ float sm[];
    float* sX   = sm;                 // 64 x PL  (normalized x chunk; later w^T)
    float* sSh  = sX + 64 * PL;       // 64 x PL  (shared, tf32)
    float* sLg  = sSh + 64 * PL;      // 64 x PL  (logits -> w fp32)
    float* sGeo = sLg + 64 * PL;      // 64 x PL  (geo, tf32)
    float* wb0  = sGeo + 64 * PL;     // stage buffer 0
    float* wb1  = wb0 + 64 * PL;      // stage buffer 1
    float* sG1  = wb1 + 64 * PL;      // 256
    float* sB1  = sG1 + 256;          // 256
    float* sMean = sB1 + 256;         // 64
    float* sRstd = sMean + 64;        // 64
    float* sBsh = sRstd + 64;         // 64
    float* sBa  = sBsh + 64;          // 64

    const int tid = threadIdx.x;
    const int warp = tid >> 5, lane = tid & 31;
    const int wr = warp >> 1, wc = warp & 1;
    const int g = lane >> 2, q = lane & 3;
    const int b = blockIdx.x / BPB, rb = blockIdx.x % BPB;
    float* wb[2] = { wb0, wb1 };

    sG1[tid] = g1[tid]; sB1[tid] = b1[tid];
    if (tid < 64) { sBsh[tid] = bsh[tid]; sBa[tid] = basn[tid]; }
    float wloc = 0.0f;
    float Macc[4][4] = {};   // persistent w^T @ shared accumulator (mma fragments)
    __syncthreads();

    for (int tile = rb; tile < NTILE; tile += BPB) {
        const size_t tok0 = (size_t)b * NTOK + (size_t)tile * TT;
        __syncthreads();   // prev tile readers of all smem done

        cp_stage(wb0, g_WshT, 64, tid);
        CP_COMMIT();

        // LN stats
#pragma unroll 1
        for (int qq = 0; qq < 8; qq++) {
            int t = warp * 8 + qq;
            const float* row = xg + (tok0 + t) * CD;
            float s1 = 0.0f, s2 = 0.0f;
#pragma unroll
            for (int k = 0; k < 8; k++) { float v = row[lane + 32 * k]; s1 += v; s2 += v * v; }
#pragma unroll
            for (int o = 16; o > 0; o >>= 1) {
                s1 += __shfl_xor_sync(~0u, s1, o);
                s2 += __shfl_xor_sync(~0u, s2, o);
            }
            if (lane == 0) {
                float m = s1 * (1.0f / 256.0f);
                sMean[t] = m;
                sRstd[t] = rsqrtf(fmaxf(s2 * (1.0f / 256.0f) - m * m, 0.0f) + 1e-5f);
            }
        }
        // geo -> sGeo (tf32)
        for (int i = tid; i < 1024; i += 256) {
            int t = i >> 4, c4 = (i & 15) * 4;
            float4 v = *reinterpret_cast<const float4*>(geo + (tok0 + t) * LD + c4);
            *reinterpret_cast<float4*>(sGeo + t * PL + c4) =
                make_float4(totf(v.x), totf(v.y), totf(v.z), totf(v.w));
        }
        __syncthreads();   // stats visible

        // GEMM1 (pipelined): shared = LN(x) @ Wsh
        float a1[4][4] = {};
#pragma unroll 1
        for (int kt = 0; kt < 4; kt++) {
            const int base = kt * 64;
#pragma unroll
            for (int ii = 0; ii < 4; ii++) {
                int idx = tid + ii * 256;
                int r = idx >> 4, c4 = (idx & 15) * 4;
                float4 xv = *reinterpret_cast<const float4*>(xg + (tok0 + r) * CD + base + c4);
                float m = sMean[r], rs = sRstd[r];
                *reinterpret_cast<float4*>(sX + r * PL + c4) = make_float4(
                    totf((xv.x - m) * rs * sG1[base + c4 + 0] + sB1[base + c4 + 0]),
                    totf((xv.y - m) * rs * sG1[base + c4 + 1] + sB1[base + c4 + 1]),
                    totf((xv.z - m) * rs * sG1[base + c4 + 2] + sB1[base + c4 + 2]),
                    totf((xv.w - m) * rs * sG1[base + c4 + 3] + sB1[base + c4 + 3]));
            }
            if (kt < 3) { cp_stage(wb[(kt + 1) & 1], g_WshT + (kt + 1) * 64 * 64, 64, tid); CP_COMMIT(); }
            if (kt < 3) { CP_WAIT(1); } else { CP_WAIT(0); }
            __syncthreads();
            mma_warp64(sX, PL, wb[kt & 1], wr, wc, g, q, a1);
            __syncthreads();
        }
        // shared -> sSh (tf32 + bias); prefetch both Wasn chunks
#pragma unroll
        for (int t = 0; t < 4; t++) {
            int col = wc * 32 + t * 8 + 2 * q;
            int r0 = (wr * 16 + g) * PL, r1 = r0 + 8 * PL;
            sSh[r0 + col]     = totf(a1[t][0] + sBsh[col]);
            sSh[r0 + col + 1] = totf(a1[t][1] + sBsh[col + 1]);
            sSh[r1 + col]     = totf(a1[t][2] + sBsh[col]);
            sSh[r1 + col + 1] = totf(a1[t][3] + sBsh[col + 1]);
        }
        cp_stage(wb0, g_WasnT, 64, tid);
        cp_stage(wb1, g_WasnT + 64 * 64, 64, tid);
        CP_COMMIT();
        CP_WAIT(0);
        __syncthreads();   // sSh + Wasn visible; sX reads done (w^T store safe)

        // GEMM3: logits = shared@Wasn0 + geo@Wasn1
        float a3[4][4] = {};
        mma_warp64(sSh, PL, wb0, wr, wc, g, q, a3);
        mma_warp64(sGeo, PL, wb1, wr, wc, g, q, a3);
#pragma unroll
        for (int t = 0; t < 4; t++) {
            int col = wc * 32 + t * 8 + 2 * q;
            int r0 = (wr * 16 + g) * PL, r1 = r0 + 8 * PL;
            sLg[r0 + col]     = a3[t][0] + sBa[col];
            sLg[r0 + col + 1] = a3[t][1] + sBa[col + 1];
            sLg[r1 + col]     = a3[t][2] + sBa[col];
            sLg[r1 + col + 1] = a3[t][3] + sBa[col + 1];
        }
        __syncthreads();

        // softmax -> w : fp32 in sLg, tf32 spill to g_w, tf32 transpose into sX (w^T)
#pragma unroll 1
        for (int qq = 0; qq < 8; qq++) {
            int t = warp * 8 + qq;
            float v0 = sLg[t * PL + lane], v1 = sLg[t * PL + lane + 32];
            float mx = fmaxf(v0, v1);
#pragma unroll
            for (int o = 16; o > 0; o >>= 1) mx = fmaxf(mx, __shfl_xor_sync(~0u, mx, o));
            float e0 = __expf(v0 - mx), e1 = __expf(v1 - mx), ss = e0 + e1;
#pragma unroll
            for (int o = 16; o > 0; o >>= 1) ss += __shfl_xor_sync(~0u, ss, o);
            float inv = 1.0f / ss;
            float w0 = e0 * inv, w1 = e1 * inv;
            float t0 = totf(w0), t1 = totf(w1);
            sLg[t * PL + lane] = w0; sLg[t * PL + lane + 32] = w1;
            sX[lane * PL + t] = t0; sX[(lane + 32) * PL + t] = t1;   // w^T
            float* wo = g_w + (tok0 + t) * SD;
            wo[lane] = t0; wo[lane + 32] = t1;
        }
        __syncthreads();

        if (tid < 64) {
            float cs = 0.0f;
            for (int t = 0; t < 64; t++) cs += sLg[t * PL + tid];
            wloc += cs;
        }
        // GEMM4': Macc += w^T @ shared  (tf32 mma, persistent fragment accumulators)
        mma_warp64(sX, PL, sSh, wr, wc, g, q, Macc);
    }

    if (tid < 64) atomicAdd(&g_wsum[b * 64 + tid], wloc);
#pragma unroll
    for (int t = 0; t < 4; t++) {
        int col = wc * 32 + t * 8 + 2 * q;
        int r0 = wr * 16 + g, r1 = r0 + 8;
        atomicAdd(&g_M[b * 4096 + r0 * 64 + col],     Macc[t][0]);
        atomicAdd(&g_M[b * 4096 + r0 * 64 + col + 1], Macc[t][1]);
        atomicAdd(&g_M[b * 4096 + r1 * 64 + col],     Macc[t][2]);
        atomicAdd(&g_M[b * 4096 + r1 * 64 + col + 1], Macc[t][3]);
    }
}

// ============================ K2: slice reconstruction + latent transition ============================
extern "C" __global__ void __launch_bounds__(256, 1)
k2(const float* __restrict__ Wfe, const float* __restrict__ bfe,
   const float* __restrict__ Wd, const float* __restrict__ bd,
   const float* __restrict__ gdn, const float* __restrict__ bdn,
   const float* __restrict__ Wanc, const float* __restrict__ banc,
   const float* __restrict__ Wself, const float* __restrict__ Wctx,
   const float* __restrict__ gon, const float* __restrict__ bon,
   const float* __restrict__ Wup, const float* __restrict__ bup)
{
    extern __shared__ float sm[];
    float* sS  = sm;               // 64 x PH
    float* sWb = sS + 64 * PH;     // 256 x PL
    float* sT1 = sWb + 256 * PL;   // 64 x PL
    float* sT2 = sT1 + 64 * PL;    // 64 x PL
    float* sCx = sT2 + 64 * PL;    // 64 x PL
    float* sAn = sCx + 64 * PL;    // 16 x PL
    float* sAw = sAn + 16 * PL;    // 64 x 20
    float* sAs = sAw + 64 * 20;    // 16
    float* sWm = sAs + 16;         // 64

    const int tid = threadIdx.x;
    const int tr = tid >> 4, tc = tid & 15;
    const int warp = tid >> 5, lane = tid & 31;
    const int b = blockIdx.x;

    if (tid < 64) sWm[tid] = fmaxf(g_wsum[b * 64 + tid], 1e-6f);
    for (int i = tid; i < 64 * 64; i += 256) {
        int s = i >> 6, l = i & 63;
        sT1[s * PL + l] = g_M[b * 4096 + i];
    }
    __syncthreads();

    for (int cc = 0; cc < 4; cc++) {
        __syncthreads();
        stage64c(sWb, Wfe + cc * 64, 256, tid);
        __syncthreads();
        float acc[4][4] = {};
        mm64(sT1, PL, sWb, PL, tr, tc, acc);
#pragma unroll
        for (int i = 0; i < 4; i++)
#pragma unroll
            for (int j = 0; j < 4; j++) {
                int s = tr + 16 * i, c = cc * 64 + tc * 4 + j;
                float ws = sWm[s];
                sS[s * PH + c] = (acc[i][j] + ws * bfe[c]) / ws;
            }
    }
    __syncthreads();

    for (int i = tid; i < 256 * 16; i += 256) {
        int r = i >> 4, c4 = (i & 15) * 4;
        *reinterpret_cast<float4*>(sWb + r * PL + c4) =
            *reinterpret_cast<const float4*>(Wd + r * 64 + c4);
    }
    __syncthreads();
    {
        float acc[4][4] = {};
        for (int kt = 0; kt < 4; kt++)
            mm64(sS + kt * 64, PH, sWb + kt * 64 * PL, PL, tr, tc, acc);
        __syncthreads();
#pragma unroll
        for (int i = 0; i < 4; i++)
#pragma unroll
            for (int j = 0; j < 4; j++) {
                int c = tc * 4 + j;
                sT2[(tr + 16 * i) * PL + c] = acc[i][j] + bd[c];
            }
    }
    __syncthreads();
    ln64(sT2, sT1, gdn, bdn, warp, lane);
    __syncthreads();

    {
        int s = tid >> 2, a0 = (tid & 3) * 4;
        float a4[4] = {0.f, 0.f, 0.f, 0.f};
        for (int k = 0; k < 64; k++) {
            float av = sT1[s * PL + k];
#pragma unroll
            for (int j = 0; j < 4; j++) a4[j] = fmaf(av, Wanc[k * 16 + a0 + j], a4[j]);
        }
#pragma unroll
        for (int j = 0; j < 4; j++) sAw[s * 20 + a0 + j] = a4[j] + banc[a0 + j];
    }
    __syncthreads();
    if (tid < 64) {
        float mx = -1e30f;
        for (int a = 0; a < 16; a++) mx = fmaxf(mx, sAw[tid * 20 + a]);
        float e[16], ss = 0.0f;
        for (int a = 0; a < 16; a++) { e[a] = __expf(sAw[tid * 20 + a] - mx); ss += e[a]; }
        float inv = 1.0f / ss;
        for (int a = 0; a < 16; a++) sAw[tid * 20 + a] = e[a] * inv;
    }
    __syncthreads();
    if (tid < 16) {
        float cs = 0.0f;
        for (int s = 0; s < 64; s++) cs += sAw[s * 20 + tid];
        sAs[tid] = fmaxf(cs, 1e-6f);
    }
    __syncthreads();
    for (int idx = tid; idx < 16 * 64; idx += 256) {
        int a = idx >> 6, d = idx & 63;
        float s = 0.0f;
        for (int t = 0; t < 64; t++) s = fmaf(sAw[t * 20 + a], sT1[t * PL + d], s);
        sAn[a * PL + d] = s / sAs[a];
    }
    __syncthreads();
    for (int idx = tid; idx < 64 * 64; idx += 256) {
        int s = idx >> 6, d = idx & 63;
        float v = 0.0f;
#pragma unroll
        for (int a = 0; a < 16; a++) v = fmaf(sAw[s * 20 + a], sAn[a * PL + d], v);
        sCx[s * PL + d] = v;
    }
    __syncthreads();

    {
        float acc[4][4] = {};
        for (int i = tid; i < 64 * 16; i += 256) {
            int r = i >> 4, c4 = (i & 15) * 4;
            *reinterpret_cast<float4*>(sWb + r * PL + c4) =
                *reinterpret_cast<const float4*>(Wself + r * 64 + c4);
        }
        __syncthreads();
        mm64(sT1, PL, sWb, PL, tr, tc, acc);
        __syncthreads();
        for (int i = tid; i < 64 * 16; i += 256) {
            int r = i >> 4, c4 = (i & 15) * 4;
            *reinterpret_cast<float4*>(sWb + r * PL + c4) =
                *reinterpret_cast<const float4*>(Wctx + r * 64 + c4);
        }
        __syncthreads();
        mm64(sCx, PL, sWb, PL, tr, tc, acc);
#pragma unroll
        for (int i = 0; i < 4; i++)
#pragma unroll
            for (int j = 0; j < 4; j++) {
                int row = tr + 16 * i, c = tc * 4 + j;
                sT2[row * PL + c] = sT1[row * PL + c] + geluf(acc[i][j]);
            }
    }
    __syncthreads();
    ln64(sT2, sCx, gon, bon, warp, lane);
    __syncthreads();

    // st = LN(ul)@Wup + bup (tf32, row-major)
    for (int cc = 0; cc < 4; cc++) {
        __syncthreads();
        for (int i = tid; i < 64 * 16; i += 256) {
            int r = i >> 4, c4 = (i & 15) * 4;
            *reinterpret_cast<float4*>(sWb + r * PL + c4) =
                *reinterpret_cast<const float4*>(Wup + r * 256 + cc * 64 + c4);
        }
        __syncthreads();
        float acc[4][4] = {};
        mm64(sCx, PL, sWb, PL, tr, tc, acc);
#pragma unroll
        for (int i = 0; i < 4; i++)
#pragma unroll
            for (int j = 0; j < 4; j++) {
                int row = tr + 16 * i, c = cc * 64 + tc * 4 + j;
                g_st[b * 16384 + row * 256 + c] = totf(acc[i][j] + bup[c]);
            }
    }
}

// ============================ K3a: y = x + w@st (st resident, fused 4-chunk mma) ============================
extern "C" __global__ void __launch_bounds__(256, 2)
k3a(const float* __restrict__ xg, float* __restrict__ out)
{
    extern __shared__ float sm[];
    float* sWt = sm;               // 64 x PL : w tile (A)
    float* sSt = sWt + 64 * PL;    // 4 chunks x (64 x PL) : st, resident

    const int tid = threadIdx.x;
    const int warp = tid >> 5, lane = tid & 31;
    const int wr = warp >> 1, wc = warp & 1;
    const int g = lane >> 2, q = lane & 3;
    const int b = blockIdx.x / BPB, rb = blockIdx.x % BPB;

    // stage st once (per-batch constant)
#pragma unroll
    for (int cc = 0; cc < 4; cc++)
        cp_stage(sSt + cc * 64 * PL, g_st + b * 16384 + cc * 64, 256, tid);
    CP_COMMIT();
    CP_WAIT(0);
    __syncthreads();

    for (int tile = rb; tile < NTILE; tile += BPB) {
        const size_t tok0 = (size_t)b * NTOK + (size_t)tile * TT;
        __syncthreads();   // prev tile's mma reads of sWt done

        cp_stage(sWt, g_w + tok0 * SD, SD, tid);
        CP_COMMIT();
        CP_WAIT(0);
        __syncthreads();   // sWt visible

        // fused mma: A fragments loaded once per k8, reused across 4 chunks
        float acc[4][4][4] = {};
#pragma unroll
        for (int k8 = 0; k8 < 8; k8++) {
            const float* Ab = sWt + (wr * 16 + g) * PL + k8 * 8 + q;
            unsigned a[4] = { __float_as_uint(Ab[0]), __float_as_uint(Ab[8 * PL]),
                              __float_as_uint(Ab[4]), __float_as_uint(Ab[8 * PL + 4]) };
#pragma unroll
            for (int cc = 0; cc < 4; cc++) {
#pragma unroll
                for (int t = 0; t < 4; t++) {
                    const float* Bb = sSt + cc * 64 * PL + (k8 * 8 + q) * PL + wc * 32 + t * 8 + g;
                    unsigned bf[2] = { __float_as_uint(Bb[0]), __float_as_uint(Bb[4 * PL]) };
                    mma8(acc[cc][t], a, bf);
                }
            }
        }
        // epilogue: y = acc + x -> out
#pragma unroll
        for (int cc = 0; cc < 4; cc++)
#pragma unroll
            for (int t = 0; t < 4; t++) {
                int col = cc * 64 + wc * 32 + t * 8 + 2 * q;
                size_t r0 = (tok0 + wr * 16 + g) * CD + col;
                size_t r1 = r0 + 8 * CD;
                float2 x0 = *reinterpret_cast<const float2*>(xg + r0);
                float2 x1 = *reinterpret_cast<const float2*>(xg + r1);
                *reinterpret_cast<float2*>(out + r0) = make_float2(acc[cc][t][0] + x0.x, acc[cc][t][1] + x0.y);
                *reinterpret_cast<float2*>(out + r1) = make_float2(acc[cc][t][2] + x1.x, acc[cc][t][3] + x1.y);
            }
    }
}

// ============================ K3b: LN2 + GLU + out-proj (pipelined, A-frag reuse) ============================
extern "C" __global__ void __launch_bounds__(256, 2)
k3b(const float* __restrict__ g2, const float* __restrict__ b2,
    const float* __restrict__ binp, const float* __restrict__ boutp,
    float* __restrict__ out)
{
    extern __shared__ float sm[];
    float* sH  = sm;               // 64 x PH : LN2(y) tf32; first 64xPL reused for act
    float* bb0 = sH + 64 * PH;     // stage buffers
    float* bb1 = bb0 + 64 * PL;
    float* sG2 = bb1 + 64 * PL;    // 256
    float* sB2 = sG2 + 256;        // 256
    float* sBi = sB2 + 256;        // 128

    const int tid = threadIdx.x;
    const int warp = tid >> 5, lane = tid & 31;
    const int wr = warp >> 1, wc = warp & 1;
    const int g = lane >> 2, q = lane & 3;
    const int b = blockIdx.x / BPB, rb = blockIdx.x % BPB;
    float* bb[2] = { bb0, bb1 };
    float* sAct = sH;              // alias, pitch PL

    sG2[tid] = g2[tid]; sB2[tid] = b2[tid];
    if (tid < 128) sBi[tid] = binp[tid];
    __syncthreads();

    for (int tile = rb; tile < NTILE; tile += BPB) {
        const size_t tok0 = (size_t)b * NTOK + (size_t)tile * TT;
        __syncthreads();   // prev tile readers done

        cp_stage(bb0, g_WinT, 128, tid);   // Win chunk (kt=0, v-half)
        CP_COMMIT();

        // LN2: y (from out, written by k3a) -> h (tf32) in sH
#pragma unroll 1
        for (int qq = 0; qq < 8; qq++) {
            int t = warp * 8 + qq;
            const float* yrow = out + (tok0 + t) * CD;
            float v[8], s1 = 0.0f, s2 = 0.0f;
#pragma unroll
            for (int k = 0; k < 8; k++) { v[k] = yrow[lane + 32 * k]; s1 += v[k]; s2 += v[k] * v[k]; }
#pragma unroll
            for (int o = 16; o > 0; o >>= 1) {
                s1 += __shfl_xor_sync(~0u, s1, o);
                s2 += __shfl_xor_sync(~0u, s2, o);
            }
            float m = s1 * (1.0f / 256.0f);
            float r = rsqrtf(fmaxf(s2 * (1.0f / 256.0f) - m * m, 0.0f) + 1e-5f);
#pragma unroll
            for (int k = 0; k < 8; k++) {
                int c = lane + 32 * k;
                sH[t * PH + c] = totf((v[k] - m) * r * sG2[c] + sB2[c]);
            }
        }
        __syncthreads();   // sH visible

        // GEMM B: vg = h @ Win (8 chunks: c = kt*2 + h); A fragments cached per kt
        unsigned afr[8][4];
        float accv[4][4] = {}, accg[4][4] = {};
#pragma unroll 1
        for (int c = 0; c < 8; c++) {
            if (c < 7) {
                int nkt = (c + 1) >> 1, nh = (c + 1) & 1;
                cp_stage(bb[(c + 1) & 1], g_WinT + nkt * 64 * 128 + nh * 64, 128, tid);
                CP_COMMIT();
            }
            if (c < 7) { CP_WAIT(1); } else { CP_WAIT(0); }
            __syncthreads();
            if (!(c & 1)) load_afrag(sH + (c >> 1) * 64, PH, wr, g, q, afr);
            if (c & 1) mma_pre(afr, bb[c & 1], wc, g, q, accg);
            else       mma_pre(afr, bb[c & 1], wc, g, q, accv);
            __syncthreads();
        }

        cp_stage(bb0, g_WoutT, 256, tid);
        CP_COMMIT();

        // act -> sAct (reuses sH start; GEMM B reads done)
#pragma unroll
        for (int t = 0; t < 4; t++) {
            int col = wc * 32 + t * 8 + 2 * q;
            int s0 = (wr * 16 + g) * PL + col;
            int s1 = s0 + 8 * PL;
            sAct[s0]     = totf(geluf(accv[t][0] + sBi[col])     * sigm(accg[t][0] + sBi[64 + col]));
            sAct[s0 + 1] = totf(geluf(accv[t][1] + sBi[col + 1]) * sigm(accg[t][1] + sBi[64 + col + 1]));
            sAct[s1]     = totf(geluf(accv[t][2] + sBi[col])     * sigm(accg[t][2] + sBi[64 + col]));
            sAct[s1 + 1] = totf(geluf(accv[t][3] + sBi[col + 1]) * sigm(accg[t][3] + sBi[64 + col + 1]));
        }

        // GEMM C: out = y + act @ Wout + bout (act fragments loaded once)
#pragma unroll 1
        for (int cc = 0; cc < 4; cc++) {
            if (cc < 3) { cp_stage(bb[(cc + 1) & 1], g_WoutT + (cc + 1) * 64, 256, tid); CP_COMMIT(); }
            if (cc < 3) { CP_WAIT(1); } else { CP_WAIT(0); }
            __syncthreads();   // act (cc=0) + staged chunk visible
            if (cc == 0) load_afrag(sAct, PL, wr, g, q, afr);
            float acc[4][4] = {};
            mma_pre(afr, bb[cc & 1], wc, g, q, acc);
#pragma unroll
            for (int t = 0; t < 4; t++) {
                int col = cc * 64 + wc * 32 + t * 8 + 2 * q;
                size_t r0 = (tok0 + wr * 16 + g) * CD + col;
                size_t r1 = r0 + 8 * CD;
                float2 y0 = *reinterpret_cast<const float2*>(out + r0);
                float2 y1 = *reinterpret_cast<const float2*>(out + r1);
                float2 bo = *reinterpret_cast<const float2*>(boutp + col);
                *reinterpret_cast<float2*>(out + r0) =
                    make_float2(y0.x + acc[t][0] + bo.x, y0.y + acc[t][1] + bo.y);
                *reinterpret_cast<float2*>(out + r1) =
                    make_float2(y1.x + acc[t][2] + bo.x, y1.y + acc[t][3] + bo.y);
            }
            __syncthreads();
        }
    }
}

// ============================ launcher ============================
extern "C" void kernel_launch(void* const* d_in, const int* in_sizes, int n_in,
                              void* d_out, int out_size)
{
    const float* x     = (const float*)d_in[0];
    const float* geo   = (const float*)d_in[1];
    const float* ln1g  = (const float*)d_in[2];
    const float* ln1b  = (const float*)d_in[3];
    const float* Wsh   = (const float*)d_in[4];
    const float* bsh   = (const float*)d_in[5];
    const float* Wfe   = (const float*)d_in[6];
    const float* bfe   = (const float*)d_in[7];
    const float* Wasn  = (const float*)d_in[8];
    const float* basn  = (const float*)d_in[9];
    const float* Wd    = (const float*)d_in[10];
    const float* bd    = (const float*)d_in[11];
    const float* gdn   = (const float*)d_in[12];
    const float* bdn   = (const float*)d_in[13];
    const float* Wanc  = (const float*)d_in[14];
    const float* banc  = (const float*)d_in[15];
    const float* Wself = (const float*)d_in[16];
    const float* Wctx  = (const float*)d_in[17];
    const float* gon   = (const float*)d_in[18];
    const float* bon   = (const float*)d_in[19];
    const float* Wup   = (const float*)d_in[20];
    const float* bup   = (const float*)d_in[21];
    const float* ln2g  = (const float*)d_in[22];
    const float* ln2b  = (const float*)d_in[23];
    const float* Win   = (const float*)d_in[24];
    const float* binp  = (const float*)d_in[25];
    const float* Wout  = (const float*)d_in[26];
    const float* boutp = (const float*)d_in[27];
    float* out = (float*)d_out;

    const size_t S1  = (size_t)(6 * 64 * PL + 2 * 256 + 4 * 64) * sizeof(float);
    const size_t S2  = (size_t)(64 * PH + 256 * PL + 3 * 64 * PL + 16 * PL + 64 * 20 + 16 + 64) * sizeof(float);
    const size_t S3a = (size_t)(5 * 64 * PL) * sizeof(float);
    const size_t S3b = (size_t)(64 * PH + 2 * 64 * PL + 2 * 256 + 128) * sizeof(float);

    cudaFuncSetAttribute(k1,  cudaFuncAttributeMaxDynamicSharedMemorySize, (int)S1);
    cudaFuncSetAttribute(k2,  cudaFuncAttributeMaxDynamicSharedMemorySize, (int)S2);
    cudaFuncSetAttribute(k3a, cudaFuncAttributeMaxDynamicSharedMemorySize, (int)S3a);
    cudaFuncSetAttribute(k3b, cudaFuncAttributeMaxDynamicSharedMemorySize, (int)S3b);

    void* pM = nullptr; void* pwsum = nullptr;
    cudaGetSymbolAddress(&pM, g_M);
    cudaGetSymbolAddress(&pwsum, g_wsum);
    cudaMemsetAsync(pM, 0, (size_t)NB * SD * LD * sizeof(float), 0);
    cudaMemsetAsync(pwsum, 0, (size_t)NB * SD * sizeof(float), 0);

    k0<<<128, 256>>>(Wsh, Wasn, Win, Wout);
    k1<<<NB * BPB, 256, S1>>>(x, geo, ln1g, ln1b, bsh, basn);
    k2<<<NB, 256, S2>>>(Wfe, bfe, Wd, bd, gdn, bdn, Wanc, banc, Wself, Wctx, gon, bon, Wup, bup);
    k3a<<<NB * BPB, 256, S3a>>>(x, out);
    k3b<<<NB * BPB, 256, S3b>>>(ln2g, ln2b, binp, boutp, out);
}